// round 1
// baseline (speedup 1.0000x reference)
#include <cuda_runtime.h>
#include <cstdint>

#define C_HID 128
#define N_EXP 4
#define BATCH 16
#define HW 6400     // 80*80
#define W80 80

// ---------------- static scratch (no allocations allowed) ----------------
__device__ float g_y[BATCH * 256 * HW];       // cv1 output (a = ch 0..127, m = ch 128..255)
__device__ float g_moe[BATCH * C_HID * HW];   // gated expert mix
__device__ float g_pooled[BATCH * C_HID];
__device__ float g_gate[BATCH * N_EXP];
__device__ float g_w1t[256 * 256];            // [ic][oc]
__device__ float g_w2t[384 * 256];            // [ic][oc]
__device__ float g_wexpt[N_EXP * 128 * 9 * 128]; // [e][ic][tap][oc]

__device__ __forceinline__ float silu_f(float v) {
    return v / (1.0f + __expf(-v));
}

// ---------------- kernel 0: weight transposes ----------------
__global__ void prep_kernel(const float* __restrict__ W1,
                            const float* __restrict__ W2,
                            const float* __restrict__ We) {
    int i = blockIdx.x * blockDim.x + threadIdx.x;
    if (i < 256 * 256) {            // W1: [oc][ic] -> [ic][oc]
        int oc = i >> 8, ic = i & 255;
        g_w1t[ic * 256 + oc] = W1[i];
    }
    if (i < 256 * 384) {            // W2: [oc][ic] -> [ic][oc]
        int oc = i / 384, ic = i % 384;
        g_w2t[ic * 256 + oc] = W2[i];
    }
    if (i < N_EXP * 128 * 128 * 9) { // We: [e][oc][ic][tap] -> [e][ic][tap][oc]
        int tap = i % 9; int r = i / 9;
        int ic = r & 127; r >>= 7;
        int oc = r & 127; int e = r >> 7;
        g_wexpt[(((e * 128 + ic) * 9) + tap) * 128 + oc] = We[i];
    }
}

// ---------------- kernel 1: cv1 = 1x1 conv + SiLU (SGEMM M=256,N=6400,K=256 per batch) ----------------
__global__ __launch_bounds__(256) void cv1_kernel(const float* __restrict__ x,
                                                  const float* __restrict__ bias) {
    int b  = blockIdx.z;
    int m0 = blockIdx.y * 64;
    int n0 = blockIdx.x * 64;
    __shared__ float Ws[16][64];
    __shared__ float Xs[16][64];
    const float* xb = x + (size_t)b * 256 * HW;

    int t = threadIdx.x;
    int tm = t >> 4, tn = t & 15;
    float acc[4][4] = {};

    int lk = t >> 4;             // 0..15  (row of the 16x64 tile)
    int ln = (t & 15) * 4;       // 0..60  (col, float4)

    for (int k0 = 0; k0 < 256; k0 += 16) {
        *(float4*)&Ws[lk][ln] = *(const float4*)&g_w1t[(k0 + lk) * 256 + m0 + ln];
        *(float4*)&Xs[lk][ln] = *(const float4*)&xb[(k0 + lk) * HW + n0 + ln];
        __syncthreads();
#pragma unroll
        for (int k = 0; k < 16; k++) {
            float4 a4 = *(float4*)&Ws[k][tm * 4];
            float4 b4 = *(float4*)&Xs[k][tn * 4];
            float av[4] = {a4.x, a4.y, a4.z, a4.w};
            float bv[4] = {b4.x, b4.y, b4.z, b4.w};
#pragma unroll
            for (int i = 0; i < 4; i++)
#pragma unroll
                for (int j = 0; j < 4; j++)
                    acc[i][j] += av[i] * bv[j];
        }
        __syncthreads();
    }
#pragma unroll
    for (int i = 0; i < 4; i++) {
        int oc = m0 + tm * 4 + i;
        float bv = bias[oc];
        float* yp = g_y + ((size_t)(b * 256 + oc)) * HW + n0 + tn * 4;
#pragma unroll
        for (int j = 0; j < 4; j++) {
            float v = acc[i][j] + bv;
            yp[j] = silu_f(v);
        }
    }
}

// ---------------- kernel 2: mean pool of m channels ----------------
__global__ void pool_kernel() {
    int idx = blockIdx.x;            // 0..16*128
    int b = idx >> 7, c = idx & 127;
    const float* p = g_y + ((size_t)(b * 256 + 128 + c)) * HW;
    float s = 0.f;
    for (int i = threadIdx.x; i < HW; i += 256) s += p[i];
    __shared__ float red[256];
    red[threadIdx.x] = s;
    __syncthreads();
    for (int off = 128; off > 0; off >>= 1) {
        if (threadIdx.x < off) red[threadIdx.x] += red[threadIdx.x + off];
        __syncthreads();
    }
    if (threadIdx.x == 0) g_pooled[b * C_HID + c] = red[0] * (1.0f / HW);
}

// ---------------- kernel 3: gating (softmax + top-2 + renorm) ----------------
__global__ void gate_kernel(const float* __restrict__ Wr, const float* __restrict__ br) {
    int b = threadIdx.x;
    if (b >= BATCH) return;
    float l[N_EXP];
#pragma unroll
    for (int e = 0; e < N_EXP; e++) {
        float s = br[e];
        for (int k = 0; k < C_HID; k++) s += g_pooled[b * C_HID + k] * Wr[e * C_HID + k];
        l[e] = s;
    }
    int i1 = 0;
#pragma unroll
    for (int e = 1; e < N_EXP; e++) if (l[e] > l[i1]) i1 = e;
    int i2 = -1;
#pragma unroll
    for (int e = 0; e < N_EXP; e++) {
        if (e == i1) continue;
        if (i2 < 0 || l[e] > l[i2]) i2 = e;
    }
    // top-2 softmax renorm: w1 = 1/(1+exp(l2-l1)), w2 = exp(l2-l1)/(1+exp(l2-l1))
    float e2 = expf(l[i2] - l[i1]);
    float inv = 1.0f / (1.0f + e2);
#pragma unroll
    for (int e = 0; e < N_EXP; e++) {
        float g = 0.f;
        if (e == i1) g = inv;
        else if (e == i2) g = e2 * inv;
        g_gate[b * N_EXP + e] = g;
    }
}

// ---------------- kernel 4: gated expert 3x3 convs + SiLU, accumulate into moe ----------------
// block: one (batch, oc-tile of 64, output row h). Threads 256: tm=t>>4 (4 oc each), tn=t&15 (5 cols each).
__global__ __launch_bounds__(256) void expert_kernel(const float* __restrict__ be) {
    int b   = blockIdx.z;
    int oc0 = blockIdx.y * 64;
    int h   = blockIdx.x;

    __shared__ float Xs[8][3][82];   // [ic][row][col+halo], col 0 == input col -1
    __shared__ float Ws[8][9][64];   // [ic][tap][oc]

    const float* mb = g_y + ((size_t)(b * 256 + 128)) * HW;

    int t = threadIdx.x;
    int tm = t >> 4;       // 0..15 -> oc = oc0 + tm*4 + i
    int tn = t & 15;       // 0..15 -> cols tn*5 .. tn*5+4

    float out[4][5] = {};

    for (int e = 0; e < N_EXP; e++) {
        float g = g_gate[b * N_EXP + e];
        if (g == 0.0f) continue;

        float acc[4][5] = {};
        for (int ic0 = 0; ic0 < 128; ic0 += 8) {
            // load input tile (8 ic x 3 rows x 82 cols with zero borders)
            for (int idx = t; idx < 8 * 3 * 82; idx += 256) {
                int ic = idx / 246;
                int rem = idx - ic * 246;
                int r = rem / 82;
                int c = rem - r * 82;
                int gr = h - 1 + r;
                int gc = c - 1;
                float v = 0.f;
                if (gr >= 0 && gr < W80 && gc >= 0 && gc < W80)
                    v = mb[(size_t)(ic0 + ic) * HW + gr * W80 + gc];
                Xs[ic][r][c] = v;
            }
            // load weights (8 ic x 9 taps x 64 oc), coalesced over oc
            for (int idx = t; idx < 8 * 9 * 64; idx += 256) {
                int ic  = idx / 576;
                int rem = idx - ic * 576;
                int tap = rem >> 6;
                int oc  = rem & 63;
                Ws[ic][tap][oc] =
                    g_wexpt[(((e * 128 + ic0 + ic) * 9) + tap) * 128 + oc0 + oc];
            }
            __syncthreads();
#pragma unroll
            for (int ic = 0; ic < 8; ic++) {
#pragma unroll
                for (int kh = 0; kh < 3; kh++) {
                    float xv[7];
#pragma unroll
                    for (int j = 0; j < 7; j++) xv[j] = Xs[ic][kh][tn * 5 + j];
#pragma unroll
                    for (int kw = 0; kw < 3; kw++) {
                        float4 w4 = *(float4*)&Ws[ic][kh * 3 + kw][tm * 4];
                        float wv[4] = {w4.x, w4.y, w4.z, w4.w};
#pragma unroll
                        for (int i = 0; i < 4; i++)
#pragma unroll
                            for (int c = 0; c < 5; c++)
                                acc[i][c] += wv[i] * xv[c + kw];
                    }
                }
            }
            __syncthreads();
        }
        // epilogue: bias + SiLU + gate, accumulate
#pragma unroll
        for (int i = 0; i < 4; i++) {
            float bv = be[e * C_HID + oc0 + tm * 4 + i];
#pragma unroll
            for (int c = 0; c < 5; c++) {
                float v = acc[i][c] + bv;
                out[i][c] += g * silu_f(v);
            }
        }
    }
#pragma unroll
    for (int i = 0; i < 4; i++) {
        float* mp = g_moe + ((size_t)(b * C_HID + oc0 + tm * 4 + i)) * HW + h * W80 + tn * 5;
#pragma unroll
        for (int c = 0; c < 5; c++) mp[c] = out[i][c];
    }
}

// ---------------- kernel 5: cv2 = 1x1 conv over concat[a,m,moe] + SiLU (K=384) ----------------
__global__ __launch_bounds__(256) void cv2_kernel(const float* __restrict__ bias,
                                                  float* __restrict__ outp) {
    int b  = blockIdx.z;
    int m0 = blockIdx.y * 64;
    int n0 = blockIdx.x * 64;
    __shared__ float Ws[16][64];
    __shared__ float Xs[16][64];

    int t = threadIdx.x;
    int tm = t >> 4, tn = t & 15;
    float acc[4][4] = {};

    int lk = t >> 4;
    int ln = (t & 15) * 4;

    for (int k0 = 0; k0 < 384; k0 += 16) {
        int kg = k0 + lk;
        const float* src;
        if (kg < 256) src = g_y   + ((size_t)(b * 256 + kg)) * HW;
        else          src = g_moe + ((size_t)(b * 128 + (kg - 256))) * HW;
        *(float4*)&Ws[lk][ln] = *(const float4*)&g_w2t[kg * 256 + m0 + ln];
        *(float4*)&Xs[lk][ln] = *(const float4*)&src[n0 + ln];
        __syncthreads();
#pragma unroll
        for (int k = 0; k < 16; k++) {
            float4 a4 = *(float4*)&Ws[k][tm * 4];
            float4 b4 = *(float4*)&Xs[k][tn * 4];
            float av[4] = {a4.x, a4.y, a4.z, a4.w};
            float bv[4] = {b4.x, b4.y, b4.z, b4.w};
#pragma unroll
            for (int i = 0; i < 4; i++)
#pragma unroll
                for (int j = 0; j < 4; j++)
                    acc[i][j] += av[i] * bv[j];
        }
        __syncthreads();
    }
#pragma unroll
    for (int i = 0; i < 4; i++) {
        int oc = m0 + tm * 4 + i;
        float bv = bias[oc];
        float* op = outp + ((size_t)(b * 256 + oc)) * HW + n0 + tn * 4;
#pragma unroll
        for (int j = 0; j < 4; j++) {
            float v = acc[i][j] + bv;
            op[j] = silu_f(v);
        }
    }
}

// ---------------- launch ----------------
extern "C" void kernel_launch(void* const* d_in, const int* in_sizes, int n_in,
                              void* d_out, int out_size) {
    const float* x  = (const float*)d_in[0];
    const float* W1 = (const float*)d_in[1];
    const float* b1 = (const float*)d_in[2];
    const float* Wr = (const float*)d_in[3];
    const float* br = (const float*)d_in[4];
    const float* We = (const float*)d_in[5];
    const float* be = (const float*)d_in[6];
    const float* W2 = (const float*)d_in[7];
    const float* b2 = (const float*)d_in[8];
    float* out = (float*)d_out;

    prep_kernel<<<(N_EXP * 128 * 128 * 9 + 255) / 256, 256>>>(W1, W2, We);
    cv1_kernel<<<dim3(100, 4, BATCH), 256>>>(x, b1);
    pool_kernel<<<BATCH * C_HID, 256>>>();
    gate_kernel<<<1, 32>>>(Wr, br);
    expert_kernel<<<dim3(80, 2, BATCH), 256>>>(be);
    cv2_kernel<<<dim3(100, 4, BATCH), 256>>>(b2, out);
}

// round 2
// speedup vs baseline: 2.3918x; 2.3918x over previous
#include <cuda_runtime.h>
#include <cstdint>

#define C_HID 128
#define N_EXP 4
#define BATCH 16
#define HW 6400     // 80*80
#define W80 80

// ---------------- static scratch (no allocations allowed) ----------------
__device__ float g_y[BATCH * 256 * HW];       // cv1 output (a = ch 0..127, m = ch 128..255)
__device__ float g_moe[BATCH * C_HID * HW];   // gated expert mix
__device__ float g_pooled[BATCH * C_HID];
__device__ float g_gate[BATCH * N_EXP];
__device__ float g_w1t[256 * 256];            // [ic][oc]
__device__ float g_w2t[384 * 256];            // [ic][oc]
__device__ float g_wexpt[N_EXP * 128 * 9 * 128]; // [e][ic][tap][oc]

__device__ __forceinline__ float silu_f(float v) {
    return v / (1.0f + __expf(-v));
}

__device__ __forceinline__ uint32_t f2tf(float f) {
    uint32_t u;
    asm("cvt.rna.tf32.f32 %0, %1;" : "=r"(u) : "f"(f));
    return u;
}

__device__ __forceinline__ void mma8(float* c, const uint32_t* a, const uint32_t* b) {
    asm volatile(
        "mma.sync.aligned.m16n8k8.row.col.f32.tf32.tf32.f32 "
        "{%0,%1,%2,%3}, {%4,%5,%6,%7}, {%8,%9}, {%0,%1,%2,%3};\n"
        : "+f"(c[0]), "+f"(c[1]), "+f"(c[2]), "+f"(c[3])
        : "r"(a[0]), "r"(a[1]), "r"(a[2]), "r"(a[3]),
          "r"(b[0]), "r"(b[1]));
}

// ---------------- kernel 0: weight transposes ----------------
__global__ void prep_kernel(const float* __restrict__ W1,
                            const float* __restrict__ W2,
                            const float* __restrict__ We) {
    int i = blockIdx.x * blockDim.x + threadIdx.x;
    if (i < 256 * 256) {            // W1: [oc][ic] -> [ic][oc]
        int oc = i >> 8, ic = i & 255;
        g_w1t[ic * 256 + oc] = W1[i];
    }
    if (i < 256 * 384) {            // W2: [oc][ic] -> [ic][oc]
        int oc = i / 384, ic = i % 384;
        g_w2t[ic * 256 + oc] = W2[i];
    }
    if (i < N_EXP * 128 * 128 * 9) { // We: [e][oc][ic][tap] -> [e][ic][tap][oc]
        int tap = i % 9; int r = i / 9;
        int ic = r & 127; r >>= 7;
        int oc = r & 127; int e = r >> 7;
        g_wexpt[(((e * 128 + ic) * 9) + tap) * 128 + oc] = We[i];
    }
}

// ---------------- cv1 / cv2: tf32 tensor-core GEMM ----------------
// Block tile M=128, N=64, K-step 32. 8 warps as 4(M) x 2(N), warp tile 32x32.
// SPLIT=false: B = x (K=256), A = g_w1t, out = g_y
// SPLIT=true:  B = concat[g_y (256), g_moe (128)] (K=384), A = g_w2t, out = outp
template <int KTOT, bool SPLIT>
__global__ __launch_bounds__(256) void cv_mma_kernel(const float* __restrict__ X,
                                                     const float* __restrict__ bias,
                                                     float* __restrict__ outp) {
    __shared__ uint32_t As[32][136];   // [k][m], stride 136 (mod 32 == 8) -> conflict-free frags
    __shared__ uint32_t Bs[32][72];    // [k][n], stride 72  (mod 32 == 8)

    const int b  = blockIdx.z;
    const int m0 = blockIdx.y * 128;
    const int n0 = blockIdx.x * 64;

    const int t    = threadIdx.x;
    const int warp = t >> 5, lane = t & 31;
    const int g    = lane >> 2, q = lane & 3;
    const int wm   = warp >> 1, wn = warp & 1;

    const float* wt = SPLIT ? g_w2t : g_w1t;

    float acc[2][4][4] = {};

    for (int k0 = 0; k0 < KTOT; k0 += 32) {
        // load A tile: 32 x 128 floats = 1024 float4
#pragma unroll
        for (int i = 0; i < 4; i++) {
            int idx = t + i * 256;
            int r = idx >> 5, c4 = (idx & 31) << 2;
            float4 v = *(const float4*)&wt[(size_t)(k0 + r) * 256 + m0 + c4];
            uint4 u = make_uint4(f2tf(v.x), f2tf(v.y), f2tf(v.z), f2tf(v.w));
            *(uint4*)&As[r][c4] = u;
        }
        // load B tile: 32 x 64 floats = 512 float4
#pragma unroll
        for (int i = 0; i < 2; i++) {
            int idx = t + i * 256;
            int r = idx >> 4, c4 = (idx & 15) << 2;
            int kg = k0 + r;
            const float* src;
            if (!SPLIT) {
                src = X + ((size_t)b * KTOT + kg) * HW + n0 + c4;
            } else {
                if (kg < 256) src = g_y   + ((size_t)(b * 256 + kg)) * HW + n0 + c4;
                else          src = g_moe + ((size_t)(b * 128 + (kg - 256))) * HW + n0 + c4;
            }
            float4 v = *(const float4*)src;
            uint4 u = make_uint4(f2tf(v.x), f2tf(v.y), f2tf(v.z), f2tf(v.w));
            *(uint4*)&Bs[r][c4] = u;
        }
        __syncthreads();

#pragma unroll
        for (int kk = 0; kk < 32; kk += 8) {
            uint32_t a[2][4], bb[4][2];
#pragma unroll
            for (int mt = 0; mt < 2; mt++) {
                int mb = wm * 32 + mt * 16;
                a[mt][0] = As[kk + q][mb + g];
                a[mt][1] = As[kk + q][mb + g + 8];
                a[mt][2] = As[kk + 4 + q][mb + g];
                a[mt][3] = As[kk + 4 + q][mb + g + 8];
            }
#pragma unroll
            for (int nt = 0; nt < 4; nt++) {
                int nb = wn * 32 + nt * 8 + g;
                bb[nt][0] = Bs[kk + q][nb];
                bb[nt][1] = Bs[kk + 4 + q][nb];
            }
#pragma unroll
            for (int mt = 0; mt < 2; mt++)
#pragma unroll
                for (int nt = 0; nt < 4; nt++)
                    mma8(acc[mt][nt], a[mt], bb[nt]);
        }
        __syncthreads();
    }

    // epilogue: bias + SiLU, write float2 pairs
    float* obase = SPLIT ? outp : g_y;
#pragma unroll
    for (int mt = 0; mt < 2; mt++) {
        int ocr = m0 + wm * 32 + mt * 16 + g;
#pragma unroll
        for (int half = 0; half < 2; half++) {
            int oc = ocr + half * 8;
            float bv = bias[oc];
            float* op = obase + ((size_t)b * 256 + oc) * HW + n0 + wn * 32;
#pragma unroll
            for (int nt = 0; nt < 4; nt++) {
                int col = nt * 8 + q * 2;
                float v0 = silu_f(acc[mt][nt][half * 2 + 0] + bv);
                float v1 = silu_f(acc[mt][nt][half * 2 + 1] + bv);
                *(float2*)&op[col] = make_float2(v0, v1);
            }
        }
    }
}

// ---------------- kernel 2: mean pool of m channels ----------------
__global__ void pool_kernel() {
    int idx = blockIdx.x;            // 0..16*128
    int b = idx >> 7, c = idx & 127;
    const float* p = g_y + ((size_t)(b * 256 + 128 + c)) * HW;
    float s = 0.f;
    for (int i = threadIdx.x; i < HW; i += 256) s += p[i];
    __shared__ float red[256];
    red[threadIdx.x] = s;
    __syncthreads();
    for (int off = 128; off > 0; off >>= 1) {
        if (threadIdx.x < off) red[threadIdx.x] += red[threadIdx.x + off];
        __syncthreads();
    }
    if (threadIdx.x == 0) g_pooled[b * C_HID + c] = red[0] * (1.0f / HW);
}

// ---------------- kernel 3: gating (softmax + top-2 + renorm), fp32 ----------------
__global__ void gate_kernel(const float* __restrict__ Wr, const float* __restrict__ br) {
    int b = threadIdx.x;
    if (b >= BATCH) return;
    float l[N_EXP];
#pragma unroll
    for (int e = 0; e < N_EXP; e++) {
        float s = br[e];
        for (int k = 0; k < C_HID; k++) s += g_pooled[b * C_HID + k] * Wr[e * C_HID + k];
        l[e] = s;
    }
    int i1 = 0;
#pragma unroll
    for (int e = 1; e < N_EXP; e++) if (l[e] > l[i1]) i1 = e;
    int i2 = -1;
#pragma unroll
    for (int e = 0; e < N_EXP; e++) {
        if (e == i1) continue;
        if (i2 < 0 || l[e] > l[i2]) i2 = e;
    }
    float e2 = expf(l[i2] - l[i1]);
    float inv = 1.0f / (1.0f + e2);
#pragma unroll
    for (int e = 0; e < N_EXP; e++) {
        float g = 0.f;
        if (e == i1) g = inv;
        else if (e == i2) g = e2 * inv;
        g_gate[b * N_EXP + e] = g;
    }
}

// ---------------- kernel 4: expert 3x3 convs via tf32 mma (implicit GEMM) ----------------
// Block = (batch b, output row h). M = 128 oc, N = 80 pixels.
// 8 warps as 4(M) x 2(N): warp tile 32 oc x 40 px (2 m-tiles x 5 n-tiles).
// K loop: 16 ic-blocks of 8; within each, 9 taps (K=8 mma each).
__global__ __launch_bounds__(256) void expert_mma_kernel(const float* __restrict__ be) {
    __shared__ uint32_t Ws[8][9][136];   // [ic][tap][oc]; ic stride 1224 (mod32==8), tap stride 136 (mod32==8)
    __shared__ uint32_t Xs[8][3][88];    // [ic][row][col+halo]; ic stride 264 (mod32==8). col c == input col c-1

    const int b = blockIdx.z;
    const int h = blockIdx.x;

    const int t    = threadIdx.x;
    const int warp = t >> 5, lane = t & 31;
    const int g    = lane >> 2, q = lane & 3;
    const int wm   = warp >> 1, wn = warp & 1;

    const float* minp = g_y + ((size_t)(b * 256 + 128)) * HW;

    bool first = true;
    for (int e = 0; e < N_EXP; e++) {
        float gt = g_gate[b * N_EXP + e];
        if (gt == 0.0f) continue;

        float acc[2][5][4] = {};

        for (int ic0 = 0; ic0 < 128; ic0 += 8) {
            // input tile: 8 ic x 3 rows x 82 cols (zero borders)
            for (int idx = t; idx < 8 * 3 * 82; idx += 256) {
                int ic = idx / 246;
                int rem = idx - ic * 246;
                int r = rem / 82;
                int c = rem - r * 82;
                int gr = h - 1 + r;
                int gc = c - 1;
                float v = 0.f;
                if ((unsigned)gr < 80u && (unsigned)gc < 80u)
                    v = minp[(size_t)(ic0 + ic) * HW + gr * W80 + gc];
                Xs[ic][r][c] = f2tf(v);
            }
            // weight tile: 8 ic x 9 taps x 128 oc = 2304 float4
#pragma unroll
            for (int i = 0; i < 9; i++) {
                int idx = t + i * 256;
                int oc4 = (idx & 31) << 2;
                int rem = idx >> 5;
                int tap = rem % 9;
                int ic  = rem / 9;
                const float* src = g_wexpt + (((size_t)(e * 128 + ic0 + ic) * 9) + tap) * 128 + oc4;
                float4 v = *(const float4*)src;
                *(uint4*)&Ws[ic][tap][oc4] = make_uint4(f2tf(v.x), f2tf(v.y), f2tf(v.z), f2tf(v.w));
            }
            __syncthreads();

#pragma unroll
            for (int tap = 0; tap < 9; tap++) {
                const int kh = tap / 3, kw = tap - kh * 3;
                uint32_t a[2][4];
#pragma unroll
                for (int mt = 0; mt < 2; mt++) {
                    int mb = wm * 32 + mt * 16;
                    a[mt][0] = Ws[q][tap][mb + g];
                    a[mt][1] = Ws[q][tap][mb + g + 8];
                    a[mt][2] = Ws[q + 4][tap][mb + g];
                    a[mt][3] = Ws[q + 4][tap][mb + g + 8];
                }
#pragma unroll
                for (int nt = 0; nt < 5; nt++) {
                    // output col x = wn*40 + nt*8 + g; input col = x-1+kw; stored at col (x+kw)
                    int xc = wn * 40 + nt * 8 + g + kw;
                    uint32_t bb[2];
                    bb[0] = Xs[q][kh][xc];
                    bb[1] = Xs[q + 4][kh][xc];
                    mma8(acc[0][nt], a[0], bb);
                    mma8(acc[1][nt], a[1], bb);
                }
            }
            __syncthreads();
        }

        // epilogue: bias + SiLU + gate; first expert stores, second accumulates (RMW)
#pragma unroll
        for (int mt = 0; mt < 2; mt++) {
            int ocr = wm * 32 + mt * 16 + g;
#pragma unroll
            for (int half = 0; half < 2; half++) {
                int oc = ocr + half * 8;
                float bv = be[e * C_HID + oc];
                float* mp = g_moe + ((size_t)(b * C_HID + oc)) * HW + h * W80 + wn * 40;
#pragma unroll
                for (int nt = 0; nt < 5; nt++) {
                    int col = nt * 8 + q * 2;
                    float v0 = gt * silu_f(acc[mt][nt][half * 2 + 0] + bv);
                    float v1 = gt * silu_f(acc[mt][nt][half * 2 + 1] + bv);
                    if (first) {
                        *(float2*)&mp[col] = make_float2(v0, v1);
                    } else {
                        float2 o = *(float2*)&mp[col];
                        o.x += v0; o.y += v1;
                        *(float2*)&mp[col] = o;
                    }
                }
            }
        }
        first = false;
    }
}

// ---------------- launch ----------------
extern "C" void kernel_launch(void* const* d_in, const int* in_sizes, int n_in,
                              void* d_out, int out_size) {
    const float* x  = (const float*)d_in[0];
    const float* W1 = (const float*)d_in[1];
    const float* b1 = (const float*)d_in[2];
    const float* Wr = (const float*)d_in[3];
    const float* br = (const float*)d_in[4];
    const float* We = (const float*)d_in[5];
    const float* be = (const float*)d_in[6];
    const float* W2 = (const float*)d_in[7];
    const float* b2 = (const float*)d_in[8];
    float* out = (float*)d_out;

    prep_kernel<<<(N_EXP * 128 * 128 * 9 + 255) / 256, 256>>>(W1, W2, We);
    cv_mma_kernel<256, false><<<dim3(100, 2, BATCH), 256>>>(x, b1, nullptr);
    pool_kernel<<<BATCH * C_HID, 256>>>();
    gate_kernel<<<1, 32>>>(Wr, br);
    expert_mma_kernel<<<dim3(80, 1, BATCH), 256>>>(be);
    cv_mma_kernel<384, true><<<dim3(100, 2, BATCH), 256>>>(nullptr, b2, out);
}

// round 3
// speedup vs baseline: 2.7734x; 1.1595x over previous
#include <cuda_runtime.h>
#include <cstdint>

#define C_HID 128
#define N_EXP 4
#define BATCH 16
#define HW 6400     // 80*80
#define W80 80

// ---------------- static scratch (no allocations allowed) ----------------
__device__ float g_y[BATCH * 256 * HW];       // cv1 output (a = ch 0..127, m = ch 128..255)
__device__ float g_moe[BATCH * C_HID * HW];   // gated expert mix
__device__ float g_pooled[BATCH * C_HID];     // channel SUMS (divided by HW in gate)
__device__ float g_gate[BATCH * N_EXP];
__device__ float g_w1t[256 * 256];            // [ic][oc]
__device__ float g_w2t[384 * 256];            // [ic][oc]
__device__ float g_wexpt[N_EXP * 128 * 9 * 128]; // [e][ic][tap][oc]

__device__ __forceinline__ float silu_f(float v) {
    return v / (1.0f + __expf(-v));
}

__device__ __forceinline__ uint32_t f2tf(float f) {
    uint32_t u;
    asm("cvt.rna.tf32.f32 %0, %1;" : "=r"(u) : "f"(f));
    return u;
}

__device__ __forceinline__ void mma8(float* c, const uint32_t* a, const uint32_t* b) {
    asm volatile(
        "mma.sync.aligned.m16n8k8.row.col.f32.tf32.tf32.f32 "
        "{%0,%1,%2,%3}, {%4,%5,%6,%7}, {%8,%9}, {%0,%1,%2,%3};\n"
        : "+f"(c[0]), "+f"(c[1]), "+f"(c[2]), "+f"(c[3])
        : "r"(a[0]), "r"(a[1]), "r"(a[2]), "r"(a[3]),
          "r"(b[0]), "r"(b[1]));
}

// ---------------- kernel 0: weight transposes + pooled zeroing ----------------
__global__ void prep_kernel(const float* __restrict__ W1,
                            const float* __restrict__ W2,
                            const float* __restrict__ We) {
    int i = blockIdx.x * blockDim.x + threadIdx.x;
    if (i < BATCH * C_HID) g_pooled[i] = 0.0f;
    if (i < 256 * 256) {            // W1: [oc][ic] -> [ic][oc]
        int oc = i >> 8, ic = i & 255;
        g_w1t[ic * 256 + oc] = W1[i];
    }
    if (i < 256 * 384) {            // W2: [oc][ic] -> [ic][oc]
        int oc = i / 384, ic = i % 384;
        g_w2t[ic * 256 + oc] = W2[i];
    }
    if (i < N_EXP * 128 * 128 * 9) { // We: [e][oc][ic][tap] -> [e][ic][tap][oc]
        int tap = i % 9; int r = i / 9;
        int ic = r & 127; r >>= 7;
        int oc = r & 127; int e = r >> 7;
        g_wexpt[(((e * 128 + ic) * 9) + tap) * 128 + oc] = We[i];
    }
}

// ---------------- cv1 / cv2: tf32 tensor-core GEMM, double-buffered ----------------
// Block tile M=128, N=64, K-step 16 (2 smem buffers). 8 warps as 4(M) x 2(N), warp tile 32x32.
// SPLIT=false: B = x (K=256), out = g_y, and (for m0==128) fused channel-sum pooling.
// SPLIT=true:  B = concat[g_y (256), g_moe (128)] (K=384), out = outp
template <int KTOT, bool SPLIT>
__global__ __launch_bounds__(256) void cv_mma_kernel(const float* __restrict__ X,
                                                     const float* __restrict__ bias,
                                                     float* __restrict__ outp) {
    __shared__ uint32_t As[2][16][136];   // [buf][k][m], stride 136 (mod32==8)
    __shared__ uint32_t Bs[2][16][72];    // [buf][k][n], stride 72  (mod32==8)

    const int b  = blockIdx.z;
    const int m0 = blockIdx.y * 128;
    const int n0 = blockIdx.x * 64;

    const int t    = threadIdx.x;
    const int warp = t >> 5, lane = t & 31;
    const int g    = lane >> 2, q = lane & 3;
    const int wm   = warp >> 1, wn = warp & 1;

    const float* wt = SPLIT ? g_w2t : g_w1t;

    float4 rA[2];   // A tile: 16x128 = 512 float4, 2/thread
    float4 rB;      // B tile: 16x64  = 256 float4, 1/thread
    const int ar0 = t >> 5,        ac0 = (t & 31) << 2;       // rA[0] slot
    const int ar1 = (t + 256) >> 5, ac1 = ac0;                // rA[1] slot
    const int br_ = t >> 4,        bc_ = (t & 15) << 2;

    float acc[2][4][4] = {};

    auto loadT = [&](int k0) {
        rA[0] = *(const float4*)&wt[(size_t)(k0 + ar0) * 256 + m0 + ac0];
        rA[1] = *(const float4*)&wt[(size_t)(k0 + ar1) * 256 + m0 + ac1];
        int kg = k0 + br_;
        const float* src;
        if (!SPLIT) {
            src = X + ((size_t)b * KTOT + kg) * HW + n0 + bc_;
        } else {
            if (kg < 256) src = g_y   + ((size_t)(b * 256 + kg)) * HW + n0 + bc_;
            else          src = g_moe + ((size_t)(b * 128 + (kg - 256))) * HW + n0 + bc_;
        }
        rB = *(const float4*)src;
    };
    auto storeT = [&](int buf) {
        *(uint4*)&As[buf][ar0][ac0] = make_uint4(f2tf(rA[0].x), f2tf(rA[0].y), f2tf(rA[0].z), f2tf(rA[0].w));
        *(uint4*)&As[buf][ar1][ac1] = make_uint4(f2tf(rA[1].x), f2tf(rA[1].y), f2tf(rA[1].z), f2tf(rA[1].w));
        *(uint4*)&Bs[buf][br_][bc_] = make_uint4(f2tf(rB.x), f2tf(rB.y), f2tf(rB.z), f2tf(rB.w));
    };

    loadT(0);
    storeT(0);
    __syncthreads();
    int cur = 0;

    for (int k0 = 0; k0 < KTOT; k0 += 16) {
        bool more = (k0 + 16 < KTOT);
        if (more) loadT(k0 + 16);
#pragma unroll
        for (int kk = 0; kk < 16; kk += 8) {
            uint32_t a[2][4], bb[4][2];
#pragma unroll
            for (int mt = 0; mt < 2; mt++) {
                int mb = wm * 32 + mt * 16;
                a[mt][0] = As[cur][kk + q][mb + g];
                a[mt][1] = As[cur][kk + q][mb + g + 8];
                a[mt][2] = As[cur][kk + 4 + q][mb + g];
                a[mt][3] = As[cur][kk + 4 + q][mb + g + 8];
            }
#pragma unroll
            for (int nt = 0; nt < 4; nt++) {
                int nb = wn * 32 + nt * 8 + g;
                bb[nt][0] = Bs[cur][kk + q][nb];
                bb[nt][1] = Bs[cur][kk + 4 + q][nb];
            }
#pragma unroll
            for (int mt = 0; mt < 2; mt++)
#pragma unroll
                for (int nt = 0; nt < 4; nt++)
                    mma8(acc[mt][nt], a[mt], bb[nt]);
        }
        if (more) storeT(cur ^ 1);
        __syncthreads();
        cur ^= 1;
    }

    // epilogue: bias + SiLU; cv1 m-half also accumulates channel sums into g_pooled
    float* obase = SPLIT ? outp : g_y;
#pragma unroll
    for (int mt = 0; mt < 2; mt++) {
#pragma unroll
        for (int half = 0; half < 2; half++) {
            int oc = m0 + wm * 32 + mt * 16 + g + half * 8;
            float bv = bias[oc];
            float* op = obase + ((size_t)b * 256 + oc) * HW + n0 + wn * 32;
            float psum = 0.f;
#pragma unroll
            for (int nt = 0; nt < 4; nt++) {
                int col = nt * 8 + q * 2;
                float v0 = silu_f(acc[mt][nt][half * 2 + 0] + bv);
                float v1 = silu_f(acc[mt][nt][half * 2 + 1] + bv);
                *(float2*)&op[col] = make_float2(v0, v1);
                psum += v0 + v1;
            }
            if (!SPLIT && m0 == 128) {
                psum += __shfl_xor_sync(0xffffffffu, psum, 1);
                psum += __shfl_xor_sync(0xffffffffu, psum, 2);
                if (q == 0) atomicAdd(&g_pooled[b * C_HID + (oc - 128)], psum);
            }
        }
    }
}

// ---------------- kernel 3: gating (softmax + top-2 + renorm), fp32 ----------------
__global__ __launch_bounds__(1024) void gate_kernel(const float* __restrict__ Wr,
                                                    const float* __restrict__ br) {
    __shared__ float lg[BATCH * N_EXP];
    const int t = threadIdx.x;
    const int w = t >> 5, lane = t & 31;
#pragma unroll
    for (int p = w; p < BATCH * N_EXP; p += 32) {
        int b = p >> 2, e = p & 3;
        float s = 0.f;
#pragma unroll
        for (int j = 0; j < 4; j++) {
            int k = lane + j * 32;
            s += g_pooled[b * C_HID + k] * Wr[e * C_HID + k];
        }
#pragma unroll
        for (int off = 16; off; off >>= 1) s += __shfl_xor_sync(0xffffffffu, s, off);
        if (lane == 0) lg[p] = s * (1.0f / HW) + br[e];
    }
    __syncthreads();
    if (t < BATCH) {
        float l[N_EXP];
#pragma unroll
        for (int e = 0; e < N_EXP; e++) l[e] = lg[t * 4 + e];
        int i1 = 0;
#pragma unroll
        for (int e = 1; e < N_EXP; e++) if (l[e] > l[i1]) i1 = e;
        int i2 = -1;
#pragma unroll
        for (int e = 0; e < N_EXP; e++) {
            if (e == i1) continue;
            if (i2 < 0 || l[e] > l[i2]) i2 = e;
        }
        float e2 = expf(l[i2] - l[i1]);
        float inv = 1.0f / (1.0f + e2);
#pragma unroll
        for (int e = 0; e < N_EXP; e++) {
            float gv = 0.f;
            if (e == i1) gv = inv;
            else if (e == i2) gv = e2 * inv;
            g_gate[t * 4 + e] = gv;
        }
    }
}

// ---------------- kernel 4: expert 3x3 convs via tf32 mma (implicit GEMM) ----------------
// Block = (batch b, row-pair hp). M = 128 oc, N = 160 (2 rows x 80 cols).
// 8 warps as 4(M) x 2(rows): warp tile 32 oc x 80 px (2 m-tiles x 10 n-tiles).
// K loop: 16 ic-blocks of 8 x 9 taps (K=8 per mma); reg-prefetch next ic-block.
__global__ __launch_bounds__(256) void expert_mma_kernel(const float* __restrict__ be) {
    // Ws flat: ic*1160 + tap*128 + oc  (ic stride 1160 == 8 mod 32 -> conflict-free frags)
    __shared__ uint32_t Ws[8 * 1160];         // 37120 B
    __shared__ uint32_t Xs[8][4][82];         // ic stride 328 == 8 mod 32; col c == input col c-1

    const int b  = blockIdx.z;
    const int hp = blockIdx.x;
    const int r0 = hp * 2;

    const int t    = threadIdx.x;
    const int warp = t >> 5, lane = t & 31;
    const int g    = lane >> 2, q = lane & 3;
    const int wm   = warp >> 1, wn = warp & 1;  // wn = output row within pair

    const float* minp = g_y + ((size_t)(b * 256 + 128)) * HW;

    float4 rW[9];
    float  rX[11];

    auto loadW = [&](int e, int ic0) {
#pragma unroll
        for (int i = 0; i < 9; i++) {
            int idx = t + i * 256;
            int oc4 = (idx & 31) << 2;
            int rem = idx >> 5;
            int tap = rem % 9;
            int ic  = rem / 9;
            rW[i] = *(const float4*)&g_wexpt[(((size_t)(e * 128 + ic0 + ic) * 9) + tap) * 128 + oc4];
        }
    };
    auto storeW = [&]() {
#pragma unroll
        for (int i = 0; i < 9; i++) {
            int idx = t + i * 256;
            int oc4 = (idx & 31) << 2;
            int rem = idx >> 5;
            int tap = rem % 9;
            int ic  = rem / 9;
            *(uint4*)&Ws[ic * 1160 + tap * 128 + oc4] =
                make_uint4(f2tf(rW[i].x), f2tf(rW[i].y), f2tf(rW[i].z), f2tf(rW[i].w));
        }
    };
    auto loadX = [&](int ic0) {
#pragma unroll
        for (int j = 0; j < 11; j++) {
            int idx = t + j * 256;
            if (idx < 8 * 4 * 82) {
                int ic  = idx / 328;
                int rem = idx - ic * 328;
                int r   = rem / 82;
                int c   = rem - r * 82;
                int gr  = r0 - 1 + r;
                int gc  = c - 1;
                float v = 0.f;
                if ((unsigned)gr < 80u && (unsigned)gc < 80u)
                    v = minp[(size_t)(ic0 + ic) * HW + gr * W80 + gc];
                rX[j] = v;
            }
        }
    };
    auto storeX = [&]() {
#pragma unroll
        for (int j = 0; j < 11; j++) {
            int idx = t + j * 256;
            if (idx < 8 * 4 * 82) {
                int ic  = idx / 328;
                int rem = idx - ic * 328;
                int r   = rem / 82;
                int c   = rem - r * 82;
                Xs[ic][r][c] = f2tf(rX[j]);
            }
        }
    };

    bool first = true;
    for (int e = 0; e < N_EXP; e++) {
        float gt = g_gate[b * N_EXP + e];
        if (gt == 0.0f) continue;

        float acc[2][10][4] = {};

        loadW(e, 0);
        loadX(0);
        for (int ic0 = 0; ic0 < 128; ic0 += 8) {
            storeW();
            storeX();
            __syncthreads();
            if (ic0 + 8 < 128) { loadW(e, ic0 + 8); loadX(ic0 + 8); }

#pragma unroll
            for (int tap = 0; tap < 9; tap++) {
                const int kh = tap / 3, kw = tap - kh * 3;
                uint32_t a[2][4];
                const uint32_t* wp0 = &Ws[q * 1160 + tap * 128];
                const uint32_t* wp4 = &Ws[(q + 4) * 1160 + tap * 128];
#pragma unroll
                for (int mt = 0; mt < 2; mt++) {
                    int mb = wm * 32 + mt * 16;
                    a[mt][0] = wp0[mb + g];
                    a[mt][1] = wp0[mb + g + 8];
                    a[mt][2] = wp4[mb + g];
                    a[mt][3] = wp4[mb + g + 8];
                }
                const int xr = wn + kh;     // tile row for output row (r0+wn), tap row kh
#pragma unroll
                for (int nt = 0; nt < 10; nt++) {
                    int xc = nt * 8 + g + kw;   // stored col of input col (nt*8+g)-1+kw
                    uint32_t bb[2];
                    bb[0] = Xs[q][xr][xc];
                    bb[1] = Xs[q + 4][xr][xc];
                    mma8(acc[0][nt], a[0], bb);
                    mma8(acc[1][nt], a[1], bb);
                }
            }
            __syncthreads();
        }

        // epilogue: bias + SiLU + gate; first active expert stores, second RMW-accumulates
        const int row = r0 + wn;
#pragma unroll
        for (int mt = 0; mt < 2; mt++) {
#pragma unroll
            for (int half = 0; half < 2; half++) {
                int oc = wm * 32 + mt * 16 + g + half * 8;
                float bv = be[e * C_HID + oc];
                float* mp = g_moe + ((size_t)(b * C_HID + oc)) * HW + row * W80;
#pragma unroll
                for (int nt = 0; nt < 10; nt++) {
                    int col = nt * 8 + q * 2;
                    float v0 = gt * silu_f(acc[mt][nt][half * 2 + 0] + bv);
                    float v1 = gt * silu_f(acc[mt][nt][half * 2 + 1] + bv);
                    if (first) {
                        *(float2*)&mp[col] = make_float2(v0, v1);
                    } else {
                        float2 o = *(float2*)&mp[col];
                        o.x += v0; o.y += v1;
                        *(float2*)&mp[col] = o;
                    }
                }
            }
        }
        first = false;
    }
}

// ---------------- launch ----------------
extern "C" void kernel_launch(void* const* d_in, const int* in_sizes, int n_in,
                              void* d_out, int out_size) {
    const float* x  = (const float*)d_in[0];
    const float* W1 = (const float*)d_in[1];
    const float* b1 = (const float*)d_in[2];
    const float* Wr = (const float*)d_in[3];
    const float* br = (const float*)d_in[4];
    const float* We = (const float*)d_in[5];
    const float* be = (const float*)d_in[6];
    const float* W2 = (const float*)d_in[7];
    const float* b2 = (const float*)d_in[8];
    float* out = (float*)d_out;

    prep_kernel<<<(N_EXP * 128 * 128 * 9 + 255) / 256, 256>>>(W1, W2, We);
    cv_mma_kernel<256, false><<<dim3(100, 2, BATCH), 256>>>(x, b1, nullptr);
    gate_kernel<<<1, 1024>>>(Wr, br);
    expert_mma_kernel<<<dim3(40, 1, BATCH), 256>>>(be);
    cv_mma_kernel<384, true><<<dim3(100, 2, BATCH), 256>>>(nullptr, b2, out);
}

// round 4
// speedup vs baseline: 3.3999x; 1.2259x over previous
#include <cuda_runtime.h>
#include <cstdint>

#define C_HID 128
#define N_EXP 4
#define BATCH 16
#define HW 6400     // 80*80
#define W80 80

// ---------------- static scratch (no allocations allowed) ----------------
__device__ float    g_y[BATCH * 256 * HW];     // cv1 out, stored as tf32 bit-patterns
__device__ float    g_moe[BATCH * C_HID * HW]; // gated expert mix, tf32 bit-patterns
__device__ float    g_pooled[BATCH * C_HID];   // channel SUMS (exact fp32)
__device__ float    g_gate[BATCH * N_EXP];
__device__ uint32_t g_w1t[256 * 256];          // [ic][P(oc)] tf32 bits
__device__ uint32_t g_w2t[384 * 256];          // [ic][P(oc)] tf32 bits
__device__ uint32_t g_wexpt[N_EXP * 128 * 9 * 128]; // [e][ic][tap][P(oc)] tf32 bits

__device__ __forceinline__ float silu_f(float v) {
    return v / (1.0f + __expf(-v));
}

__device__ __forceinline__ uint32_t f2tf(float f) {
    uint32_t u;
    asm("cvt.rna.tf32.f32 %0, %1;" : "=r"(u) : "f"(f));
    return u;
}

__device__ __forceinline__ void mma8(float* c, const uint32_t* a, const uint32_t* b) {
    asm volatile(
        "mma.sync.aligned.m16n8k8.row.col.f32.tf32.tf32.f32 "
        "{%0,%1,%2,%3}, {%4,%5,%6,%7}, {%8,%9}, {%0,%1,%2,%3};\n"
        : "+f"(c[0]), "+f"(c[1]), "+f"(c[2]), "+f"(c[3])
        : "r"(a[0]), "r"(a[1]), "r"(a[2]), "r"(a[3]),
          "r"(b[0]), "r"(b[1]));
}

__device__ __forceinline__ void cp16(uint32_t s, const void* g) {
    asm volatile("cp.async.cg.shared.global [%0], [%1], 16;\n" :: "r"(s), "l"(g));
}
__device__ __forceinline__ void cp4z(uint32_t s, const void* g, int srcsz) {
    asm volatile("cp.async.ca.shared.global [%0], [%1], 4, %2;\n" :: "r"(s), "l"(g), "r"(srcsz));
}
#define CP_COMMIT() asm volatile("cp.async.commit_group;\n" ::: "memory")
#define CP_WAIT1()  asm volatile("cp.async.wait_group 1;\n" ::: "memory")
#define CP_WAIT0()  asm volatile("cp.async.wait_group 0;\n" ::: "memory")

// oc permutation within 16-groups: logical l -> position 2*(l%8) + (l/8),
// so fragment pairs (g, g+8) sit at adjacent positions (2g, 2g+1) -> LDS.64.
__device__ __forceinline__ int permOC(int oc) {
    return (oc & ~15) | ((oc & 7) << 1) | ((oc >> 3) & 1);
}

// ---------------- kernel 0: weight transpose + tf32 convert + oc-permute ----------------
__global__ void prep_kernel(const float* __restrict__ W1,
                            const float* __restrict__ W2,
                            const float* __restrict__ We) {
    int i = blockIdx.x * blockDim.x + threadIdx.x;
    if (i < BATCH * C_HID) g_pooled[i] = 0.0f;
    if (i < 256 * 256) {            // W1: [oc][ic] -> [ic][P(oc)]
        int oc = i >> 8, ic = i & 255;
        g_w1t[ic * 256 + permOC(oc)] = f2tf(W1[i]);
    }
    if (i < 256 * 384) {            // W2: [oc][ic] -> [ic][P(oc)]
        int oc = i / 384, ic = i % 384;
        g_w2t[ic * 256 + permOC(oc)] = f2tf(W2[i]);
    }
    if (i < N_EXP * 128 * 128 * 9) { // We: [e][oc][ic][tap] -> [e][ic][tap][P(oc)]
        int tap = i % 9; int r = i / 9;
        int ic = r & 127; r >>= 7;
        int oc = r & 127; int e = r >> 7;
        g_wexpt[(((e * 128 + ic) * 9) + tap) * 128 + permOC(oc)] = f2tf(We[i]);
    }
}

// ---------------- cv1 / cv2: tf32 mma GEMM, cp.async double-buffered ----------------
// Block tile M=128, N=64, K-step 16. 8 warps 4(M) x 2(N), warp tile 32x32.
// PRECONV_B=false: cv1, B = x (fp32, reg path + cvt), out = g_y tf32 bits + fused pooling
// PRECONV_B=true:  cv2, B = concat[g_y, g_moe] tf32 bits (cp.async), out = fp32
template <int KTOT, bool PRECONV_B>
__global__ __launch_bounds__(256) void cv_mma_kernel(const float* __restrict__ X,
                                                     const float* __restrict__ bias,
                                                     float* __restrict__ outp) {
    __shared__ uint32_t As[2][16][136];   // stride 136 (mod32==8)
    __shared__ uint32_t Bs[2][16][72];    // stride 72  (mod32==8)

    const int b  = blockIdx.z;
    const int m0 = blockIdx.y * 128;
    const int n0 = blockIdx.x * 64;

    const int t    = threadIdx.x;
    const int warp = t >> 5, lane = t & 31;
    const int g    = lane >> 2, q = lane & 3;
    const int wm   = warp >> 1, wn = warp & 1;

    const uint32_t* wt = PRECONV_B ? g_w2t : g_w1t;
    const uint32_t* yb  = (const uint32_t*)g_y;
    const uint32_t* mob = (const uint32_t*)g_moe;

    const int ar = t >> 5, ac4 = (t & 31) << 2;
    const int br_ = t >> 4, bc_ = (t & 15) << 2;

    float4 rB;   // cv1 only
    float acc[2][4][4] = {};

    auto issueA = [&](int k0, int buf) {
#pragma unroll
        for (int i = 0; i < 2; i++) {
            int r = ar + i * 8;
            uint32_t d = (uint32_t)__cvta_generic_to_shared(&As[buf][r][ac4]);
            cp16(d, wt + (size_t)(k0 + r) * 256 + m0 + ac4);
        }
    };
    auto issueB = [&](int k0, int buf) {   // cv2 only
        int kg = k0 + br_;
        const uint32_t* src = (kg < 256)
            ? (yb  + ((size_t)(b * 256 + kg)) * HW + n0 + bc_)
            : (mob + ((size_t)(b * 128 + (kg - 256))) * HW + n0 + bc_);
        cp16((uint32_t)__cvta_generic_to_shared(&Bs[buf][br_][bc_]), src);
    };
    auto loadB = [&](int k0) {             // cv1 only
        rB = *(const float4*)&X[((size_t)b * KTOT + k0 + br_) * HW + n0 + bc_];
    };
    auto storeB = [&](int buf) {           // cv1 only
        *(uint4*)&Bs[buf][br_][bc_] = make_uint4(f2tf(rB.x), f2tf(rB.y), f2tf(rB.z), f2tf(rB.w));
    };

    // prologue
    issueA(0, 0);
    if (PRECONV_B) issueB(0, 0);
    CP_COMMIT();
    if (!PRECONV_B) { loadB(0); storeB(0); }

    for (int k0 = 0; k0 < KTOT; k0 += 16) {
        const int buf = (k0 >> 4) & 1;
        const bool more = (k0 + 16 < KTOT);
        if (more) {
            issueA(k0 + 16, buf ^ 1);
            if (PRECONV_B) issueB(k0 + 16, buf ^ 1);
            CP_COMMIT();
            if (!PRECONV_B) loadB(k0 + 16);
        }
        if (more) CP_WAIT1(); else CP_WAIT0();
        __syncthreads();

#pragma unroll
        for (int kk = 0; kk < 16; kk += 8) {
            uint32_t a[2][4], bb[4][2];
#pragma unroll
            for (int mt = 0; mt < 2; mt++) {
                int mb = wm * 32 + mt * 16 + 2 * g;
                uint2 lo = *(const uint2*)&As[buf][kk + q][mb];
                uint2 hi = *(const uint2*)&As[buf][kk + 4 + q][mb];
                a[mt][0] = lo.x; a[mt][1] = lo.y; a[mt][2] = hi.x; a[mt][3] = hi.y;
            }
#pragma unroll
            for (int nt = 0; nt < 4; nt++) {
                int nb = wn * 32 + nt * 8 + g;
                bb[nt][0] = Bs[buf][kk + q][nb];
                bb[nt][1] = Bs[buf][kk + 4 + q][nb];
            }
#pragma unroll
            for (int mt = 0; mt < 2; mt++)
#pragma unroll
                for (int nt = 0; nt < 4; nt++)
                    mma8(acc[mt][nt], a[mt], bb[nt]);
        }
        if (more && !PRECONV_B) storeB(buf ^ 1);
        __syncthreads();
    }

    // epilogue
#pragma unroll
    for (int mt = 0; mt < 2; mt++) {
#pragma unroll
        for (int half = 0; half < 2; half++) {
            int oc = m0 + wm * 32 + mt * 16 + g + half * 8;
            float bv = bias[oc];
            float psum = 0.f;
            if (PRECONV_B) {
                float* op = outp + ((size_t)b * 256 + oc) * HW + n0 + wn * 32;
#pragma unroll
                for (int nt = 0; nt < 4; nt++) {
                    int col = nt * 8 + q * 2;
                    float v0 = silu_f(acc[mt][nt][half * 2 + 0] + bv);
                    float v1 = silu_f(acc[mt][nt][half * 2 + 1] + bv);
                    *(float2*)&op[col] = make_float2(v0, v1);
                }
            } else {
                uint32_t* op = (uint32_t*)g_y + ((size_t)b * 256 + oc) * HW + n0 + wn * 32;
#pragma unroll
                for (int nt = 0; nt < 4; nt++) {
                    int col = nt * 8 + q * 2;
                    float v0 = silu_f(acc[mt][nt][half * 2 + 0] + bv);
                    float v1 = silu_f(acc[mt][nt][half * 2 + 1] + bv);
                    *(uint2*)&op[col] = make_uint2(f2tf(v0), f2tf(v1));
                    psum += v0 + v1;
                }
                if (m0 == 128) {
                    psum += __shfl_xor_sync(0xffffffffu, psum, 1);
                    psum += __shfl_xor_sync(0xffffffffu, psum, 2);
                    if (q == 0) atomicAdd(&g_pooled[b * C_HID + (oc - 128)], psum);
                }
            }
        }
    }
}

// ---------------- kernel 3: gating (softmax + top-2 + renorm), fp32 ----------------
__global__ __launch_bounds__(1024) void gate_kernel(const float* __restrict__ Wr,
                                                    const float* __restrict__ br) {
    __shared__ float lg[BATCH * N_EXP];
    const int t = threadIdx.x;
    const int w = t >> 5, lane = t & 31;
#pragma unroll
    for (int p = w; p < BATCH * N_EXP; p += 32) {
        int b = p >> 2, e = p & 3;
        float s = 0.f;
#pragma unroll
        for (int j = 0; j < 4; j++) {
            int k = lane + j * 32;
            s += g_pooled[b * C_HID + k] * Wr[e * C_HID + k];
        }
#pragma unroll
        for (int off = 16; off; off >>= 1) s += __shfl_xor_sync(0xffffffffu, s, off);
        if (lane == 0) lg[p] = s * (1.0f / HW) + br[e];
    }
    __syncthreads();
    if (t < BATCH) {
        float l[N_EXP];
#pragma unroll
        for (int e = 0; e < N_EXP; e++) l[e] = lg[t * 4 + e];
        int i1 = 0;
#pragma unroll
        for (int e = 1; e < N_EXP; e++) if (l[e] > l[i1]) i1 = e;
        int i2 = -1;
#pragma unroll
        for (int e = 0; e < N_EXP; e++) {
            if (e == i1) continue;
            if (i2 < 0 || l[e] > l[i2]) i2 = e;
        }
        float e2 = expf(l[i2] - l[i1]);
        float inv = 1.0f / (1.0f + e2);
#pragma unroll
        for (int e = 0; e < N_EXP; e++) {
            float gv = 0.f;
            if (e == i1) gv = inv;
            else if (e == i2) gv = e2 * inv;
            g_gate[t * 4 + e] = gv;
        }
    }
}

// ---------------- kernel 4: expert 3x3 convs, cp.async pipelined tf32 mma ----------------
// Block = (batch, row-pair). M=128 oc, N=160 (2 rows x 80). 8 warps 4(M)x2(row).
// Dynamic smem: Ws 2 x 8ic x (9*128+8) + Xs 2 x 8ic x (4*82) u32 = 95232 B.
#define WS_IC   1160                 // 9*128+8, ==8 mod 32
#define WS_BUF  (8 * WS_IC)          // 9280
#define XS_IC   328                  // 4*82, ==8 mod 32
#define XS_BUF  (8 * XS_IC)          // 2624
#define XS_BASE (2 * WS_BUF)         // 18560
#define EXP_SMEM ((XS_BASE + 2 * XS_BUF) * 4)   // 95232 bytes

__global__ __launch_bounds__(256, 2) void expert_mma_kernel(const float* __restrict__ be) {
    extern __shared__ uint32_t dsm[];

    const int b  = blockIdx.z;
    const int r0 = blockIdx.x * 2;

    const int t    = threadIdx.x;
    const int warp = t >> 5, lane = t & 31;
    const int g    = lane >> 2, q = lane & 3;
    const int wm   = warp >> 1, wn = warp & 1;

    const uint32_t* minp = (const uint32_t*)g_y + ((size_t)(b * 256 + 128)) * HW; // tf32 bits
    const uint32_t smem0 = (uint32_t)__cvta_generic_to_shared(dsm);

    const int oc4 = (t & 31) << 2;
    const int w0  = t >> 5;

    auto issueStage = [&](int e, int ic0, int buf) {
        // weights: 2304 float4
        uint32_t wdst = smem0 + (buf * WS_BUF) * 4;
#pragma unroll
        for (int i = 0; i < 9; i++) {
            int rem = w0 + i * 8;         // 0..71
            int tap = rem % 9, ic = rem / 9;
            cp16(wdst + (uint32_t)(ic * WS_IC + tap * 128 + oc4) * 4,
                 g_wexpt + ((size_t)((e * 128 + ic0 + ic) * 9) + tap) * 128 + oc4);
        }
        // input: 2624 x 4B with border zero-fill (flat idx == dst offset)
        uint32_t xdst = smem0 + (XS_BASE + buf * XS_BUF) * 4;
#pragma unroll
        for (int j = 0; j < 11; j++) {
            int idx = t + j * 256;
            if (idx < 8 * XS_IC) {
                int ic  = idx / XS_IC;
                int rem = idx - ic * XS_IC;
                int r   = rem / 82;
                int c   = rem - r * 82;
                int gr  = r0 - 1 + r;
                int gc  = c - 1;
                bool ok = ((unsigned)gr < 80u) && ((unsigned)gc < 80u);
                const uint32_t* src = minp + (size_t)(ic0 + ic) * HW + (ok ? gr * W80 + gc : 0);
                cp4z(xdst + (uint32_t)idx * 4, src, ok ? 4 : 0);
            }
        }
        CP_COMMIT();
    };

    bool first = true;
    for (int e = 0; e < N_EXP; e++) {
        float gt = g_gate[b * N_EXP + e];
        if (gt == 0.0f) continue;

        float acc[2][10][4] = {};

        issueStage(e, 0, 0);
        for (int ic0 = 0; ic0 < 128; ic0 += 8) {
            const int buf = (ic0 >> 3) & 1;
            const bool more = (ic0 + 8 < 128);
            if (more) issueStage(e, ic0 + 8, buf ^ 1);
            if (more) CP_WAIT1(); else CP_WAIT0();
            __syncthreads();

            const uint32_t* Wb = dsm + buf * WS_BUF;
            const uint32_t* Xb = dsm + XS_BASE + buf * XS_BUF;
#pragma unroll
            for (int tap = 0; tap < 9; tap++) {
                const int kh = tap / 3, kw = tap - kh * 3;
                uint32_t a[2][4];
                const uint32_t* wq0 = Wb + q * WS_IC + tap * 128;
                const uint32_t* wq4 = Wb + (q + 4) * WS_IC + tap * 128;
#pragma unroll
                for (int mt = 0; mt < 2; mt++) {
                    int mb = wm * 32 + mt * 16 + 2 * g;
                    uint2 lo = *(const uint2*)(wq0 + mb);
                    uint2 hi = *(const uint2*)(wq4 + mb);
                    a[mt][0] = lo.x; a[mt][1] = lo.y; a[mt][2] = hi.x; a[mt][3] = hi.y;
                }
                const uint32_t* xq0 = Xb + q * XS_IC + (wn + kh) * 82;
                const uint32_t* xq4 = Xb + (q + 4) * XS_IC + (wn + kh) * 82;
#pragma unroll
                for (int nt = 0; nt < 10; nt++) {
                    int xc = nt * 8 + g + kw;
                    uint32_t bb[2] = { xq0[xc], xq4[xc] };
                    mma8(acc[0][nt], a[0], bb);
                    mma8(acc[1][nt], a[1], bb);
                }
            }
            __syncthreads();
        }

        // epilogue: bias + SiLU + gate; store tf32 bits; 2nd expert RMW-accumulates
        const int row = r0 + wn;
#pragma unroll
        for (int mt = 0; mt < 2; mt++) {
#pragma unroll
            for (int half = 0; half < 2; half++) {
                int oc = wm * 32 + mt * 16 + g + half * 8;
                float bv = be[e * C_HID + oc];
                float* mp = g_moe + ((size_t)(b * C_HID + oc)) * HW + row * W80;
#pragma unroll
                for (int nt = 0; nt < 10; nt++) {
                    int col = nt * 8 + q * 2;
                    float v0 = gt * silu_f(acc[mt][nt][half * 2 + 0] + bv);
                    float v1 = gt * silu_f(acc[mt][nt][half * 2 + 1] + bv);
                    if (!first) {
                        float2 o = *(float2*)&mp[col];
                        v0 += o.x; v1 += o.y;
                    }
                    *(uint2*)&mp[col] = make_uint2(f2tf(v0), f2tf(v1));
                }
            }
        }
        first = false;
    }
}

// ---------------- launch ----------------
extern "C" void kernel_launch(void* const* d_in, const int* in_sizes, int n_in,
                              void* d_out, int out_size) {
    const float* x  = (const float*)d_in[0];
    const float* W1 = (const float*)d_in[1];
    const float* b1 = (const float*)d_in[2];
    const float* Wr = (const float*)d_in[3];
    const float* br = (const float*)d_in[4];
    const float* We = (const float*)d_in[5];
    const float* be = (const float*)d_in[6];
    const float* W2 = (const float*)d_in[7];
    const float* b2 = (const float*)d_in[8];
    float* out = (float*)d_out;

    cudaFuncSetAttribute(expert_mma_kernel,
                         cudaFuncAttributeMaxDynamicSharedMemorySize, EXP_SMEM);

    prep_kernel<<<(N_EXP * 128 * 128 * 9 + 255) / 256, 256>>>(W1, W2, We);
    cv_mma_kernel<256, false><<<dim3(100, 2, BATCH), 256>>>(x, b1, nullptr);
    gate_kernel<<<1, 1024>>>(Wr, br);
    expert_mma_kernel<<<dim3(40, 1, BATCH), 256, EXP_SMEM>>>(be);
    cv_mma_kernel<384, true><<<dim3(100, 2, BATCH), 256>>>(nullptr, b2, out);
}

// round 5
// speedup vs baseline: 5.6697x; 1.6676x over previous
#include <cuda_runtime.h>
#include <cuda_fp16.h>
#include <cstdint>

#define C_HID 128
#define N_EXP 4
#define BATCH 16
#define HW 6400     // 80*80
#define W80 80

// ---------------- static scratch (no allocations allowed) ----------------
// half2 channel-pair packed activations: [b][cpair][pix] as u32(half2(c_even, c_odd))
__device__ uint32_t g_y2[BATCH * 128 * HW];     // cv1 out (a: cp 0..63, m: cp 64..127)
__device__ uint32_t g_moe2[BATCH * 64 * HW];    // gated expert mix
__device__ float    g_pooled[BATCH * C_HID];    // channel SUMS (exact fp32)
__device__ float    g_gate[BATCH * N_EXP];
// half2 k-pair packed weights, oc-permuted
__device__ uint32_t g_w1t2[128 * 256];          // [kp][P(oc)]
__device__ uint32_t g_w2t2[192 * 256];          // [kp][P(oc)]
__device__ uint32_t g_wexpt2[N_EXP * 64 * 9 * 128]; // [e][icp][tap][P(oc)]

__device__ __forceinline__ float silu_f(float v) {
    return v / (1.0f + __expf(-v));
}

__device__ __forceinline__ uint32_t packh2(float lo, float hi) {
    __half2 h = __floats2half2_rn(lo, hi);
    return *(uint32_t*)&h;
}

// m16n8k16 fp16 -> fp32 accum
__device__ __forceinline__ void mma16(float* c, const uint32_t* a, const uint32_t* b) {
    asm volatile(
        "mma.sync.aligned.m16n8k16.row.col.f32.f16.f16.f32 "
        "{%0,%1,%2,%3}, {%4,%5,%6,%7}, {%8,%9}, {%0,%1,%2,%3};\n"
        : "+f"(c[0]), "+f"(c[1]), "+f"(c[2]), "+f"(c[3])
        : "r"(a[0]), "r"(a[1]), "r"(a[2]), "r"(a[3]),
          "r"(b[0]), "r"(b[1]));
}

__device__ __forceinline__ void cp16(uint32_t s, const void* g) {
    asm volatile("cp.async.cg.shared.global [%0], [%1], 16;\n" :: "r"(s), "l"(g));
}
__device__ __forceinline__ void cp4z(uint32_t s, const void* g, int srcsz) {
    asm volatile("cp.async.ca.shared.global [%0], [%1], 4, %2;\n" :: "r"(s), "l"(g), "r"(srcsz));
}
#define CP_COMMIT() asm volatile("cp.async.commit_group;\n" ::: "memory")
#define CP_WAIT1()  asm volatile("cp.async.wait_group 1;\n" ::: "memory")
#define CP_WAIT0()  asm volatile("cp.async.wait_group 0;\n" ::: "memory")

// oc permutation within 16-groups: logical l -> 2*(l%8) + (l/8); fragment pair (g, g+8) adjacent.
__device__ __forceinline__ int permOC(int oc) {
    return (oc & ~15) | ((oc & 7) << 1) | ((oc >> 3) & 1);
}

// ---------------- kernel 0: weight transpose + half2 pack + oc-permute ----------------
__global__ void prep_kernel(const float* __restrict__ W1,
                            const float* __restrict__ W2,
                            const float* __restrict__ We) {
    int i = blockIdx.x * blockDim.x + threadIdx.x;
    if (i < BATCH * C_HID) g_pooled[i] = 0.0f;
    if (i < 128 * 256) {            // W1 [oc][ic] -> [kp][P(oc)] half2(ic=2kp, 2kp+1)
        int kp = i >> 8, oc = i & 255;
        g_w1t2[kp * 256 + permOC(oc)] = packh2(W1[oc * 256 + 2 * kp], W1[oc * 256 + 2 * kp + 1]);
    }
    if (i < 192 * 256) {            // W2 [oc][ic] -> [kp][P(oc)]
        int kp = i >> 8, oc = i & 255;
        g_w2t2[kp * 256 + permOC(oc)] = packh2(W2[oc * 384 + 2 * kp], W2[oc * 384 + 2 * kp + 1]);
    }
    if (i < N_EXP * 64 * 9 * 128) { // We [e][oc][ic][tap] -> [e][icp][tap][P(oc)]
        int oc = i & 127; int r = i >> 7;
        int tap = r % 9; r /= 9;
        int icp = r & 63; int e = r >> 6;
        size_t sb = ((size_t)(e * 128 + oc) * 128 + 2 * icp) * 9 + tap;
        g_wexpt2[(((e * 64 + icp) * 9) + tap) * 128 + permOC(oc)] = packh2(We[sb], We[sb + 9]);
    }
}

// ---------------- cv1 / cv2: fp16 mma GEMM, cp.async double-buffered ----------------
// Block tile M=128, N=64, stage = 16 kp (32 k). 8 warps 4(M) x 2(N), warp tile 32x32.
// PRECONV_B=false: cv1, B = x fp32 (reg load + pack), out = g_y2 half2 + fused pooling
// PRECONV_B=true:  cv2, B = concat[g_y2, g_moe2] (cp.async), out = fp32
template <int KPT, bool PRECONV_B>
__global__ __launch_bounds__(256) void cv_mma_kernel(const float* __restrict__ X,
                                                     const float* __restrict__ bias,
                                                     float* __restrict__ outp) {
    __shared__ uint32_t As[2][16][136];   // [buf][kp][P(m)], stride 136 (mod32==8)
    __shared__ uint32_t Bs[2][16][72];    // [buf][kp][n],    stride 72  (mod32==8)

    const int b  = blockIdx.z;
    const int m0 = blockIdx.y * 128;
    const int n0 = blockIdx.x * 64;

    const int t    = threadIdx.x;
    const int warp = t >> 5, lane = t & 31;
    const int g    = lane >> 2, q = lane & 3;
    const int wm   = warp >> 1, wn = warp & 1;

    const uint32_t* wt = PRECONV_B ? g_w2t2 : g_w1t2;

    const int ar = t >> 5, ac4 = (t & 31) << 2;
    const int br_ = t >> 4, bc4 = (t & 15) << 2;

    float4 rBlo, rBhi;   // cv1 only
    float acc[2][4][4] = {};

    auto issueA = [&](int kp0, int buf) {
#pragma unroll
        for (int i = 0; i < 2; i++) {
            int r = ar + i * 8;
            cp16((uint32_t)__cvta_generic_to_shared(&As[buf][r][ac4]),
                 wt + (size_t)(kp0 + r) * 256 + m0 + ac4);
        }
    };
    auto issueB = [&](int kp0, int buf) {   // cv2
        int kgp = kp0 + br_;
        const uint32_t* src = (kgp < 128)
            ? (g_y2   + ((size_t)(b * 128 + kgp)) * HW + n0 + bc4)
            : (g_moe2 + ((size_t)(b * 64 + (kgp - 128))) * HW + n0 + bc4);
        cp16((uint32_t)__cvta_generic_to_shared(&Bs[buf][br_][bc4]), src);
    };
    auto loadB = [&](int kp0) {             // cv1: two fp32 channel rows
        const float* p = X + ((size_t)b * 256 + 2 * (kp0 + br_)) * HW + n0 + bc4;
        rBlo = *(const float4*)p;
        rBhi = *(const float4*)(p + HW);
    };
    auto storeB = [&](int buf) {
        *(uint4*)&Bs[buf][br_][bc4] = make_uint4(
            packh2(rBlo.x, rBhi.x), packh2(rBlo.y, rBhi.y),
            packh2(rBlo.z, rBhi.z), packh2(rBlo.w, rBhi.w));
    };

    issueA(0, 0);
    if (PRECONV_B) issueB(0, 0);
    CP_COMMIT();
    if (!PRECONV_B) { loadB(0); storeB(0); }

    const int NST = KPT / 16;
    for (int s = 0; s < NST; s++) {
        const int buf = s & 1;
        const bool more = (s + 1 < NST);
        if (more) {
            issueA((s + 1) * 16, buf ^ 1);
            if (PRECONV_B) issueB((s + 1) * 16, buf ^ 1);
            CP_COMMIT();
            if (!PRECONV_B) loadB((s + 1) * 16);
        }
        if (more) CP_WAIT1(); else CP_WAIT0();
        __syncthreads();

#pragma unroll
        for (int kk = 0; kk < 16; kk += 8) {
            uint32_t a[2][4], bb[4][2];
#pragma unroll
            for (int mt = 0; mt < 2; mt++) {
                int mb = wm * 32 + mt * 16 + 2 * g;
                uint2 lo = *(const uint2*)&As[buf][kk + q][mb];
                uint2 hi = *(const uint2*)&As[buf][kk + 4 + q][mb];
                a[mt][0] = lo.x; a[mt][1] = lo.y; a[mt][2] = hi.x; a[mt][3] = hi.y;
            }
#pragma unroll
            for (int nt = 0; nt < 4; nt++) {
                int nb = wn * 32 + nt * 8 + g;
                bb[nt][0] = Bs[buf][kk + q][nb];
                bb[nt][1] = Bs[buf][kk + 4 + q][nb];
            }
#pragma unroll
            for (int mt = 0; mt < 2; mt++)
#pragma unroll
                for (int nt = 0; nt < 4; nt++)
                    mma16(acc[mt][nt], a[mt], bb[nt]);
        }
        if (more && !PRECONV_B) storeB(buf ^ 1);
        __syncthreads();
    }

    // epilogue
#pragma unroll
    for (int mt = 0; mt < 2; mt++) {
#pragma unroll
        for (int half = 0; half < 2; half++) {
            int oc = m0 + wm * 32 + mt * 16 + g + half * 8;
            float bv = bias[oc];
            if (PRECONV_B) {
                float* op = outp + ((size_t)b * 256 + oc) * HW + n0 + wn * 32;
#pragma unroll
                for (int nt = 0; nt < 4; nt++) {
                    int col = nt * 8 + q * 2;
                    float v0 = silu_f(acc[mt][nt][half * 2 + 0] + bv);
                    float v1 = silu_f(acc[mt][nt][half * 2 + 1] + bv);
                    *(float2*)&op[col] = make_float2(v0, v1);
                }
            } else {
                uint32_t* yp = g_y2 + ((size_t)b * 128 + (oc >> 1)) * HW + n0 + wn * 32;
                float psum = 0.f;
#pragma unroll
                for (int nt = 0; nt < 4; nt++) {
                    int col = nt * 8 + q * 2;
                    float v0 = silu_f(acc[mt][nt][half * 2 + 0] + bv);
                    float v1 = silu_f(acc[mt][nt][half * 2 + 1] + bv);
                    psum += v0 + v1;
                    // pair channels (oc even in lane g, oc+1 in lane g^1): shfl over g bit0
                    float pv0 = __shfl_xor_sync(0xffffffffu, v0, 4);
                    float pv1 = __shfl_xor_sync(0xffffffffu, v1, 4);
                    if ((g & 1) == 0)
                        *(uint2*)&yp[col] = make_uint2(packh2(v0, pv0), packh2(v1, pv1));
                }
                if (m0 == 128) {
                    psum += __shfl_xor_sync(0xffffffffu, psum, 1);
                    psum += __shfl_xor_sync(0xffffffffu, psum, 2);
                    if (q == 0) atomicAdd(&g_pooled[b * C_HID + (oc - 128)], psum);
                }
            }
        }
    }
}

// ---------------- kernel 3: gating (softmax + top-2 + renorm), fp32 ----------------
__global__ __launch_bounds__(1024) void gate_kernel(const float* __restrict__ Wr,
                                                    const float* __restrict__ br) {
    __shared__ float lg[BATCH * N_EXP];
    const int t = threadIdx.x;
    const int w = t >> 5, lane = t & 31;
#pragma unroll
    for (int p = w; p < BATCH * N_EXP; p += 32) {
        int b = p >> 2, e = p & 3;
        float s = 0.f;
#pragma unroll
        for (int j = 0; j < 4; j++) {
            int k = lane + j * 32;
            s += g_pooled[b * C_HID + k] * Wr[e * C_HID + k];
        }
#pragma unroll
        for (int off = 16; off; off >>= 1) s += __shfl_xor_sync(0xffffffffu, s, off);
        if (lane == 0) lg[p] = s * (1.0f / HW) + br[e];
    }
    __syncthreads();
    if (t < BATCH) {
        float l[N_EXP];
#pragma unroll
        for (int e = 0; e < N_EXP; e++) l[e] = lg[t * 4 + e];
        int i1 = 0;
#pragma unroll
        for (int e = 1; e < N_EXP; e++) if (l[e] > l[i1]) i1 = e;
        int i2 = -1;
#pragma unroll
        for (int e = 0; e < N_EXP; e++) {
            if (e == i1) continue;
            if (i2 < 0 || l[e] > l[i2]) i2 = e;
        }
        float e2 = expf(l[i2] - l[i1]);
        float inv = 1.0f / (1.0f + e2);
#pragma unroll
        for (int e = 0; e < N_EXP; e++) {
            float gv = 0.f;
            if (e == i1) gv = inv;
            else if (e == i2) gv = e2 * inv;
            g_gate[t * 4 + e] = gv;
        }
    }
}

// ---------------- kernel 4: expert 3x3 convs, fp16 mma, cp.async pipelined ----------------
// Block = (batch, row-pair). M=128 oc, N=160 (2 rows x 80). 8 warps 4(M)x2(row).
// Stage = 8 icp (16 ic); 8 stages. smem identical footprint to tf32 version.
#define WS_ICP  1160                 // 9*128+8, ==8 mod 32
#define WS_BUF  (8 * WS_ICP)         // 9280
#define XS_ICP  328                  // 4*82, ==8 mod 32
#define XS_BUF  (8 * XS_ICP)         // 2624
#define XS_BASE (2 * WS_BUF)         // 18560
#define EXP_SMEM ((XS_BASE + 2 * XS_BUF) * 4)   // 95232 bytes

__global__ __launch_bounds__(256, 2) void expert_mma_kernel(const float* __restrict__ be) {
    extern __shared__ uint32_t dsm[];

    const int b  = blockIdx.z;
    const int r0 = blockIdx.x * 2;

    const int t    = threadIdx.x;
    const int warp = t >> 5, lane = t & 31;
    const int g    = lane >> 2, q = lane & 3;
    const int wm   = warp >> 1, wn = warp & 1;

    const uint32_t* minp = g_y2 + ((size_t)(b * 128 + 64)) * HW;  // m channels, pair-packed
    const uint32_t smem0 = (uint32_t)__cvta_generic_to_shared(dsm);

    const int oc4 = (t & 31) << 2;
    const int w0  = t >> 5;

    auto issueStage = [&](int e, int icp0, int buf) {
        uint32_t wdst = smem0 + (buf * WS_BUF) * 4;
#pragma unroll
        for (int i = 0; i < 9; i++) {
            int rem = w0 + i * 8;         // 0..71
            int tap = rem % 9, icp = rem / 9;
            cp16(wdst + (uint32_t)(icp * WS_ICP + tap * 128 + oc4) * 4,
                 g_wexpt2 + ((size_t)((e * 64 + icp0 + icp) * 9) + tap) * 128 + oc4);
        }
        uint32_t xdst = smem0 + (XS_BASE + buf * XS_BUF) * 4;
#pragma unroll
        for (int j = 0; j < 11; j++) {
            int idx = t + j * 256;
            if (idx < 8 * XS_ICP) {
                int icp = idx / XS_ICP;
                int rem = idx - icp * XS_ICP;
                int r   = rem / 82;
                int c   = rem - r * 82;
                int gr  = r0 - 1 + r;
                int gc  = c - 1;
                bool ok = ((unsigned)gr < 80u) && ((unsigned)gc < 80u);
                const uint32_t* src = minp + (size_t)(icp0 + icp) * HW + (ok ? gr * W80 + gc : 0);
                cp4z(xdst + (uint32_t)idx * 4, src, ok ? 4 : 0);
            }
        }
        CP_COMMIT();
    };

    bool first = true;
    for (int e = 0; e < N_EXP; e++) {
        float gt = g_gate[b * N_EXP + e];
        if (gt == 0.0f) continue;

        float acc[2][10][4] = {};

        issueStage(e, 0, 0);
        for (int s = 0; s < 8; s++) {
            const int buf = s & 1;
            const bool more = (s + 1 < 8);
            if (more) issueStage(e, (s + 1) * 8, buf ^ 1);
            if (more) CP_WAIT1(); else CP_WAIT0();
            __syncthreads();

            const uint32_t* Wb = dsm + buf * WS_BUF;
            const uint32_t* Xb = dsm + XS_BASE + buf * XS_BUF;
#pragma unroll
            for (int tap = 0; tap < 9; tap++) {
                const int kh = tap / 3, kw = tap - kh * 3;
                uint32_t a[2][4];
                const uint32_t* wq0 = Wb + q * WS_ICP + tap * 128;
                const uint32_t* wq4 = Wb + (q + 4) * WS_ICP + tap * 128;
#pragma unroll
                for (int mt = 0; mt < 2; mt++) {
                    int mb = wm * 32 + mt * 16 + 2 * g;
                    uint2 lo = *(const uint2*)(wq0 + mb);
                    uint2 hi = *(const uint2*)(wq4 + mb);
                    a[mt][0] = lo.x; a[mt][1] = lo.y; a[mt][2] = hi.x; a[mt][3] = hi.y;
                }
                const uint32_t* xq0 = Xb + q * XS_ICP + (wn + kh) * 82;
                const uint32_t* xq4 = Xb + (q + 4) * XS_ICP + (wn + kh) * 82;
#pragma unroll
                for (int nt = 0; nt < 10; nt++) {
                    int xc = nt * 8 + g + kw;
                    uint32_t bb[2] = { xq0[xc], xq4[xc] };
                    mma16(acc[0][nt], a[0], bb);
                    mma16(acc[1][nt], a[1], bb);
                }
            }
            __syncthreads();
        }

        // epilogue: bias + SiLU + gate; pair-pack to half2; 2nd expert RMW-accumulates
        const int row = r0 + wn;
#pragma unroll
        for (int mt = 0; mt < 2; mt++) {
#pragma unroll
            for (int half = 0; half < 2; half++) {
                int oc = wm * 32 + mt * 16 + g + half * 8;
                float bv = be[e * C_HID + oc];
                uint32_t* mp = g_moe2 + ((size_t)(b * 64 + (oc >> 1))) * HW + row * W80;
#pragma unroll
                for (int nt = 0; nt < 10; nt++) {
                    int col = nt * 8 + q * 2;
                    float v0 = gt * silu_f(acc[mt][nt][half * 2 + 0] + bv);
                    float v1 = gt * silu_f(acc[mt][nt][half * 2 + 1] + bv);
                    float pv0 = __shfl_xor_sync(0xffffffffu, v0, 4);
                    float pv1 = __shfl_xor_sync(0xffffffffu, v1, 4);
                    if ((g & 1) == 0) {
                        if (!first) {
                            uint2 o = *(uint2*)&mp[col];
                            __half2 h0 = *(__half2*)&o.x, h1 = *(__half2*)&o.y;
                            v0  += __low2float(h0);  pv0 += __high2float(h0);
                            v1  += __low2float(h1);  pv1 += __high2float(h1);
                        }
                        *(uint2*)&mp[col] = make_uint2(packh2(v0, pv0), packh2(v1, pv1));
                    }
                }
            }
        }
        first = false;
    }
}

// ---------------- launch ----------------
extern "C" void kernel_launch(void* const* d_in, const int* in_sizes, int n_in,
                              void* d_out, int out_size) {
    const float* x  = (const float*)d_in[0];
    const float* W1 = (const float*)d_in[1];
    const float* b1 = (const float*)d_in[2];
    const float* Wr = (const float*)d_in[3];
    const float* br = (const float*)d_in[4];
    const float* We = (const float*)d_in[5];
    const float* be = (const float*)d_in[6];
    const float* W2 = (const float*)d_in[7];
    const float* b2 = (const float*)d_in[8];
    float* out = (float*)d_out;

    cudaFuncSetAttribute(expert_mma_kernel,
                         cudaFuncAttributeMaxDynamicSharedMemorySize, EXP_SMEM);

    prep_kernel<<<(N_EXP * 64 * 9 * 128 + 255) / 256, 256>>>(W1, W2, We);
    cv_mma_kernel<128, false><<<dim3(100, 2, BATCH), 256>>>(x, b1, nullptr);
    gate_kernel<<<1, 1024>>>(Wr, br);
    expert_mma_kernel<<<dim3(40, 1, BATCH), 256, EXP_SMEM>>>(be);
    cv_mma_kernel<192, true><<<dim3(100, 2, BATCH), 256>>>(nullptr, b2, out);
}

// round 12
// speedup vs baseline: 5.8378x; 1.0297x over previous
#include <cuda_runtime.h>
#include <cuda_fp16.h>
#include <cstdint>

#define C_HID 128
#define N_EXP 4
#define BATCH 16
#define HW 6400     // 80*80
#define W80 80

// ---------------- static scratch (no allocations allowed) ----------------
// half2 channel-pair packed activations: [b][cpair][pix] as u32(half2(c_even, c_odd))
__device__ uint32_t g_y2[BATCH * 128 * HW];     // cv1 out (a: cp 0..63, m: cp 64..127)
__device__ uint32_t g_moe2[BATCH * 64 * HW];    // gated expert mix
__device__ float    g_pooled[BATCH * C_HID];    // channel SUMS (exact fp32)
// half2 k-pair packed weights, oc-permuted
__device__ uint32_t g_w1t2[128 * 256];          // [kp][P(oc)]
__device__ uint32_t g_w2t2[192 * 256];          // [kp][P(oc)]
__device__ uint32_t g_wexpt2[N_EXP * 64 * 9 * 128]; // [e][icp][tap][P(oc)]

__device__ __forceinline__ float silu_f(float v) {
    return v / (1.0f + __expf(-v));
}

__device__ __forceinline__ uint32_t packh2(float lo, float hi) {
    __half2 h = __floats2half2_rn(lo, hi);
    return *(uint32_t*)&h;
}

// m16n8k16 fp16 -> fp32 accum
__device__ __forceinline__ void mma16(float* c, const uint32_t* a, const uint32_t* b) {
    asm volatile(
        "mma.sync.aligned.m16n8k16.row.col.f32.f16.f16.f32 "
        "{%0,%1,%2,%3}, {%4,%5,%6,%7}, {%8,%9}, {%0,%1,%2,%3};\n"
        : "+f"(c[0]), "+f"(c[1]), "+f"(c[2]), "+f"(c[3])
        : "r"(a[0]), "r"(a[1]), "r"(a[2]), "r"(a[3]),
          "r"(b[0]), "r"(b[1]));
}

__device__ __forceinline__ void cp16(uint32_t s, const void* g) {
    asm volatile("cp.async.cg.shared.global [%0], [%1], 16;\n" :: "r"(s), "l"(g));
}
__device__ __forceinline__ void cp4z(uint32_t s, const void* g, int srcsz) {
    asm volatile("cp.async.ca.shared.global [%0], [%1], 4, %2;\n" :: "r"(s), "l"(g), "r"(srcsz));
}
#define CP_COMMIT() asm volatile("cp.async.commit_group;\n" ::: "memory")
#define CP_WAIT1()  asm volatile("cp.async.wait_group 1;\n" ::: "memory")
#define CP_WAIT0()  asm volatile("cp.async.wait_group 0;\n" ::: "memory")

// oc permutation within 16-groups: logical l -> 2*(l%8) + (l/8); fragment pair (g, g+8) adjacent.
__device__ __forceinline__ int permOC(int oc) {
    return (oc & ~15) | ((oc & 7) << 1) | ((oc >> 3) & 1);
}

// ---------------- kernel 0: weight transpose + half2 pack + oc-permute ----------------
__global__ void prep_kernel(const float* __restrict__ W1,
                            const float* __restrict__ W2,
                            const float* __restrict__ We) {
    cudaTriggerProgrammaticLaunchCompletion();
    int i = blockIdx.x * blockDim.x + threadIdx.x;
    if (i < BATCH * C_HID) g_pooled[i] = 0.0f;
    if (i < 128 * 256) {            // W1 [oc][ic] -> [kp][P(oc)] half2(ic=2kp, 2kp+1)
        int kp = i >> 8, oc = i & 255;
        g_w1t2[kp * 256 + permOC(oc)] = packh2(W1[oc * 256 + 2 * kp], W1[oc * 256 + 2 * kp + 1]);
    }
    if (i < 192 * 256) {            // W2 [oc][ic] -> [kp][P(oc)]
        int kp = i >> 8, oc = i & 255;
        g_w2t2[kp * 256 + permOC(oc)] = packh2(W2[oc * 384 + 2 * kp], W2[oc * 384 + 2 * kp + 1]);
    }
    if (i < N_EXP * 64 * 9 * 128) { // We [e][oc][ic][tap] -> [e][icp][tap][P(oc)]
        int oc = i & 127; int r = i >> 7;
        int tap = r % 9; r /= 9;
        int icp = r & 63; int e = r >> 6;
        size_t sb = ((size_t)(e * 128 + oc) * 128 + 2 * icp) * 9 + tap;
        g_wexpt2[(((e * 64 + icp) * 9) + tap) * 128 + permOC(oc)] = packh2(We[sb], We[sb + 9]);
    }
}

// ---------------- cv1 / cv2: fp16 mma GEMM, cp.async double-buffered ----------------
// Block tile M=128, N=64, stage = 16 kp (32 k). 8 warps 4(M) x 2(N), warp tile 32x32.
// PRECONV_B=false: cv1 (PDL: prefetch x, sync on prep), out = g_y2 half2 + fused pooling
// PRECONV_B=true:  cv2 (PDL: y2-stages run early, sync on expert before moe stages), out = fp32
template <int KPT, bool PRECONV_B>
__global__ __launch_bounds__(256) void cv_mma_kernel(const float* __restrict__ X,
                                                     const float* __restrict__ bias,
                                                     float* __restrict__ outp) {
    __shared__ uint32_t As[2][16][136];   // [buf][kp][P(m)], stride 136 (mod32==8)
    __shared__ uint32_t Bs[2][16][72];    // [buf][kp][n],    stride 72  (mod32==8)

    const int b  = blockIdx.z;
    const int m0 = blockIdx.y * 128;
    const int n0 = blockIdx.x * 64;

    const int t    = threadIdx.x;
    const int warp = t >> 5, lane = t & 31;
    const int g    = lane >> 2, q = lane & 3;
    const int wm   = warp >> 1, wn = warp & 1;

    const uint32_t* wt = PRECONV_B ? g_w2t2 : g_w1t2;

    const int ar = t >> 5, ac4 = (t & 31) << 2;
    const int br_ = t >> 4, bc4 = (t & 15) << 2;

    float4 rBlo, rBhi;   // cv1 only
    float acc[2][4][4] = {};

    auto issueA = [&](int kp0, int buf) {
#pragma unroll
        for (int i = 0; i < 2; i++) {
            int r = ar + i * 8;
            cp16((uint32_t)__cvta_generic_to_shared(&As[buf][r][ac4]),
                 wt + (size_t)(kp0 + r) * 256 + m0 + ac4);
        }
    };
    auto issueB = [&](int kp0, int buf) {   // cv2
        int kgp = kp0 + br_;
        const uint32_t* src = (kgp < 128)
            ? (g_y2   + ((size_t)(b * 128 + kgp)) * HW + n0 + bc4)
            : (g_moe2 + ((size_t)(b * 64 + (kgp - 128))) * HW + n0 + bc4);
        cp16((uint32_t)__cvta_generic_to_shared(&Bs[buf][br_][bc4]), src);
    };
    auto loadB = [&](int kp0) {             // cv1: two fp32 channel rows
        const float* p = X + ((size_t)b * 256 + 2 * (kp0 + br_)) * HW + n0 + bc4;
        rBlo = *(const float4*)p;
        rBhi = *(const float4*)(p + HW);
    };
    auto storeB = [&](int buf) {
        *(uint4*)&Bs[buf][br_][bc4] = make_uint4(
            packh2(rBlo.x, rBhi.x), packh2(rBlo.y, rBhi.y),
            packh2(rBlo.z, rBhi.z), packh2(rBlo.w, rBhi.w));
    };

    // PDL prologue
    cudaTriggerProgrammaticLaunchCompletion();
    if (!PRECONV_B) {
        loadB(0);                         // x is a harness input: independent of prep
        cudaGridDependencySynchronize();  // wait prep (weights, pooled zero)
    }
    // cv2: no top sync — y2/w2t2 are safe transitively (expert triggers after ITS sync)

    issueA(0, 0);
    if (PRECONV_B) issueB(0, 0);
    CP_COMMIT();
    if (!PRECONV_B) storeB(0);

    const int NST = KPT / 16;
    for (int s = 0; s < NST; s++) {
        const int buf = s & 1;
        const bool more = (s + 1 < NST);
        if (more) {
            if constexpr (PRECONV_B) {
                if (s == 7) cudaGridDependencySynchronize();   // before first moe-stage issue
            }
            issueA((s + 1) * 16, buf ^ 1);
            if (PRECONV_B) issueB((s + 1) * 16, buf ^ 1);
            CP_COMMIT();
            if (!PRECONV_B) loadB((s + 1) * 16);
        }
        if (more) CP_WAIT1(); else CP_WAIT0();
        __syncthreads();

#pragma unroll
        for (int kk = 0; kk < 16; kk += 8) {
            uint32_t a[2][4], bb[4][2];
#pragma unroll
            for (int mt = 0; mt < 2; mt++) {
                int mb = wm * 32 + mt * 16 + 2 * g;
                uint2 lo = *(const uint2*)&As[buf][kk + q][mb];
                uint2 hi = *(const uint2*)&As[buf][kk + 4 + q][mb];
                a[mt][0] = lo.x; a[mt][1] = lo.y; a[mt][2] = hi.x; a[mt][3] = hi.y;
            }
#pragma unroll
            for (int nt = 0; nt < 4; nt++) {
                int nb = wn * 32 + nt * 8 + g;
                bb[nt][0] = Bs[buf][kk + q][nb];
                bb[nt][1] = Bs[buf][kk + 4 + q][nb];
            }
#pragma unroll
            for (int mt = 0; mt < 2; mt++)
#pragma unroll
                for (int nt = 0; nt < 4; nt++)
                    mma16(acc[mt][nt], a[mt], bb[nt]);
        }
        if (more && !PRECONV_B) storeB(buf ^ 1);
        __syncthreads();
    }

    // epilogue
#pragma unroll
    for (int mt = 0; mt < 2; mt++) {
#pragma unroll
        for (int half = 0; half < 2; half++) {
            int oc = m0 + wm * 32 + mt * 16 + g + half * 8;
            float bv = bias[oc];
            if (PRECONV_B) {
                float* op = outp + ((size_t)b * 256 + oc) * HW + n0 + wn * 32;
#pragma unroll
                for (int nt = 0; nt < 4; nt++) {
                    int col = nt * 8 + q * 2;
                    float v0 = silu_f(acc[mt][nt][half * 2 + 0] + bv);
                    float v1 = silu_f(acc[mt][nt][half * 2 + 1] + bv);
                    *(float2*)&op[col] = make_float2(v0, v1);
                }
            } else {
                uint32_t* yp = g_y2 + ((size_t)b * 128 + (oc >> 1)) * HW + n0 + wn * 32;
                float psum = 0.f;
#pragma unroll
                for (int nt = 0; nt < 4; nt++) {
                    int col = nt * 8 + q * 2;
                    float v0 = silu_f(acc[mt][nt][half * 2 + 0] + bv);
                    float v1 = silu_f(acc[mt][nt][half * 2 + 1] + bv);
                    psum += v0 + v1;
                    // pair channels (oc even in lane g, oc+1 in lane g^1): shfl over g bit0
                    float pv0 = __shfl_xor_sync(0xffffffffu, v0, 4);
                    float pv1 = __shfl_xor_sync(0xffffffffu, v1, 4);
                    if ((g & 1) == 0)
                        *(uint2*)&yp[col] = make_uint2(packh2(v0, pv0), packh2(v1, pv1));
                }
                if (m0 == 128) {
                    psum += __shfl_xor_sync(0xffffffffu, psum, 1);
                    psum += __shfl_xor_sync(0xffffffffu, psum, 2);
                    if (q == 0) atomicAdd(&g_pooled[b * C_HID + (oc - 128)], psum);
                }
            }
        }
    }
}

// ---------------- kernel 4: expert 3x3 convs, fp16 mma, fused gating, PDL ----------------
// Block = (row-pair, 1, batch). M=128 oc, N=160 (2 rows x 80). 8 warps 4(M)x2(row).
// Stage = 8 icp (16 ic); 8 stages.
#define WS_ICP  1160                 // 9*128+8, ==8 mod 32
#define WS_BUF  (8 * WS_ICP)         // 9280
#define XS_ICP  328                  // 4*82, ==8 mod 32
#define XS_BUF  (8 * XS_ICP)         // 2624
#define XS_BASE (2 * WS_BUF)         // 18560
#define EXP_SMEM ((XS_BASE + 2 * XS_BUF) * 4)   // 95232 bytes

__global__ __launch_bounds__(256, 2) void expert_mma_kernel(const float* __restrict__ be,
                                                            const float* __restrict__ Wr,
                                                            const float* __restrict__ br) {
    extern __shared__ uint32_t dsm[];
    __shared__ float lg[N_EXP];
    __shared__ int   s_ae[2];
    __shared__ float s_ag[2];

    const int b  = blockIdx.z;
    const int r0 = blockIdx.x * 2;

    const int t    = threadIdx.x;
    const int warp = t >> 5, lane = t & 31;
    const int g    = lane >> 2, q = lane & 3;
    const int wm   = warp >> 1, wn = warp & 1;

    // PDL: wait for cv1 (pooled + y2), THEN trigger so cv2's early start implies cv1 done.
    cudaGridDependencySynchronize();
    cudaTriggerProgrammaticLaunchCompletion();

    // fused gating (redundant per block; deterministic — same pooled inputs everywhere)
    if (warp < N_EXP) {
        float s = 0.f;
#pragma unroll
        for (int j = 0; j < 4; j++) {
            int k = lane + j * 32;
            s += g_pooled[b * C_HID + k] * Wr[warp * C_HID + k];
        }
#pragma unroll
        for (int off = 16; off; off >>= 1) s += __shfl_xor_sync(0xffffffffu, s, off);
        if (lane == 0) lg[warp] = s * (1.0f / HW) + br[warp];
    }
    __syncthreads();
    if (t == 0) {
        float l[N_EXP];
#pragma unroll
        for (int e = 0; e < N_EXP; e++) l[e] = lg[e];
        int i1 = 0;
#pragma unroll
        for (int e = 1; e < N_EXP; e++) if (l[e] > l[i1]) i1 = e;
        int i2 = -1;
#pragma unroll
        for (int e = 0; e < N_EXP; e++) {
            if (e == i1) continue;
            if (i2 < 0 || l[e] > l[i2]) i2 = e;
        }
        float e2 = expf(l[i2] - l[i1]);
        float inv = 1.0f / (1.0f + e2);
        s_ae[0] = i1; s_ag[0] = inv;
        s_ae[1] = i2; s_ag[1] = e2 * inv;
    }
    __syncthreads();

    const uint32_t* minp = g_y2 + ((size_t)(b * 128 + 64)) * HW;  // m channels, pair-packed
    const uint32_t smem0 = (uint32_t)__cvta_generic_to_shared(dsm);

    const int oc4 = (t & 31) << 2;
    const int w0  = t >> 5;

    auto issueStage = [&](int e, int icp0, int buf) {
        uint32_t wdst = smem0 + (buf * WS_BUF) * 4;
#pragma unroll
        for (int i = 0; i < 9; i++) {
            int rem = w0 + i * 8;         // 0..71
            int tap = rem % 9, icp = rem / 9;
            cp16(wdst + (uint32_t)(icp * WS_ICP + tap * 128 + oc4) * 4,
                 g_wexpt2 + ((size_t)((e * 64 + icp0 + icp) * 9) + tap) * 128 + oc4);
        }
        uint32_t xdst = smem0 + (XS_BASE + buf * XS_BUF) * 4;
#pragma unroll
        for (int j = 0; j < 11; j++) {
            int idx = t + j * 256;
            if (idx < 8 * XS_ICP) {
                int icp = idx / XS_ICP;
                int rem = idx - icp * XS_ICP;
                int r   = rem / 82;
                int c   = rem - r * 82;
                int gr  = r0 - 1 + r;
                int gc  = c - 1;
                bool ok = ((unsigned)gr < 80u) && ((unsigned)gc < 80u);
                const uint32_t* src = minp + (size_t)(icp0 + icp) * HW + (ok ? gr * W80 + gc : 0);
                cp4z(xdst + (uint32_t)idx * 4, src, ok ? 4 : 0);
            }
        }
        CP_COMMIT();
    };

    for (int ei = 0; ei < 2; ei++) {
        const int   e  = s_ae[ei];
        const float gt = s_ag[ei];
        const bool first = (ei == 0);

        float acc[2][10][4] = {};

        issueStage(e, 0, 0);
        for (int s = 0; s < 8; s++) {
            const int buf = s & 1;
            const bool more = (s + 1 < 8);
            if (more) issueStage(e, (s + 1) * 8, buf ^ 1);
            if (more) CP_WAIT1(); else CP_WAIT0();
            __syncthreads();

            const uint32_t* Wb = dsm + buf * WS_BUF;
            const uint32_t* Xb = dsm + XS_BASE + buf * XS_BUF;
#pragma unroll
            for (int tap = 0; tap < 9; tap++) {
                const int kh = tap / 3, kw = tap - kh * 3;
                uint32_t a[2][4];
                const uint32_t* wq0 = Wb + q * WS_ICP + tap * 128;
                const uint32_t* wq4 = Wb + (q + 4) * WS_ICP + tap * 128;
#pragma unroll
                for (int mt = 0; mt < 2; mt++) {
                    int mb = wm * 32 + mt * 16 + 2 * g;
                    uint2 lo = *(const uint2*)(wq0 + mb);
                    uint2 hi = *(const uint2*)(wq4 + mb);
                    a[mt][0] = lo.x; a[mt][1] = lo.y; a[mt][2] = hi.x; a[mt][3] = hi.y;
                }
                const uint32_t* xq0 = Xb + q * XS_ICP + (wn + kh) * 82;
                const uint32_t* xq4 = Xb + (q + 4) * XS_ICP + (wn + kh) * 82;
#pragma unroll
                for (int nt = 0; nt < 10; nt++) {
                    int xc = nt * 8 + g + kw;
                    uint32_t bb[2] = { xq0[xc], xq4[xc] };
                    mma16(acc[0][nt], a[0], bb);
                    mma16(acc[1][nt], a[1], bb);
                }
            }
            __syncthreads();
        }

        // epilogue: bias + SiLU + gate; pair-pack to half2; 2nd expert RMW-accumulates
        const int row = r0 + wn;
#pragma unroll
        for (int mt = 0; mt < 2; mt++) {
#pragma unroll
            for (int half = 0; half < 2; half++) {
                int oc = wm * 32 + mt * 16 + g + half * 8;
                float bv = be[e * C_HID + oc];
                uint32_t* mp = g_moe2 + ((size_t)(b * 64 + (oc >> 1))) * HW + row * W80;
#pragma unroll
                for (int nt = 0; nt < 10; nt++) {
                    int col = nt * 8 + q * 2;
                    float v0 = gt * silu_f(acc[mt][nt][half * 2 + 0] + bv);
                    float v1 = gt * silu_f(acc[mt][nt][half * 2 + 1] + bv);
                    float pv0 = __shfl_xor_sync(0xffffffffu, v0, 4);
                    float pv1 = __shfl_xor_sync(0xffffffffu, v1, 4);
                    if ((g & 1) == 0) {
                        if (!first) {
                            uint2 o = *(uint2*)&mp[col];
                            __half2 h0 = *(__half2*)&o.x, h1 = *(__half2*)&o.y;
                            v0  += __low2float(h0);  pv0 += __high2float(h0);
                            v1  += __low2float(h1);  pv1 += __high2float(h1);
                        }
                        *(uint2*)&mp[col] = make_uint2(packh2(v0, pv0), packh2(v1, pv1));
                    }
                }
            }
        }
    }
}

// ---------------- launch: single stream, PDL-chained ----------------
extern "C" void kernel_launch(void* const* d_in, const int* in_sizes, int n_in,
                              void* d_out, int out_size) {
    const float* x  = (const float*)d_in[0];
    const float* W1 = (const float*)d_in[1];
    const float* b1 = (const float*)d_in[2];
    const float* Wr = (const float*)d_in[3];
    const float* br = (const float*)d_in[4];
    const float* We = (const float*)d_in[5];
    const float* be = (const float*)d_in[6];
    const float* W2 = (const float*)d_in[7];
    const float* b2 = (const float*)d_in[8];
    float* out = (float*)d_out;

    cudaFuncSetAttribute(expert_mma_kernel,
                         cudaFuncAttributeMaxDynamicSharedMemorySize, EXP_SMEM);

    cudaLaunchAttribute pdl[1];
    pdl[0].id = cudaLaunchAttributeProgrammaticStreamSerialization;
    pdl[0].val.programmaticStreamSerializationAllowed = 1;

    // prep (primary)
    prep_kernel<<<(N_EXP * 64 * 9 * 128 + 255) / 256, 256>>>(W1, W2, We);

    // cv1 (PDL secondary of prep)
    {
        cudaLaunchConfig_t cfg = {};
        cfg.gridDim = dim3(100, 2, BATCH);
        cfg.blockDim = dim3(256, 1, 1);
        cfg.attrs = pdl; cfg.numAttrs = 1;
        cudaLaunchKernelEx(&cfg, cv_mma_kernel<128, false>, x, b1, (float*)nullptr);
    }
    // expert (PDL secondary of cv1; gating fused)
    {
        cudaLaunchConfig_t cfg = {};
        cfg.gridDim = dim3(40, 1, BATCH);
        cfg.blockDim = dim3(256, 1, 1);
        cfg.dynamicSmemBytes = EXP_SMEM;
        cfg.attrs = pdl; cfg.numAttrs = 1;
        cudaLaunchKernelEx(&cfg, expert_mma_kernel, be, Wr, br);
    }
    // cv2 (PDL secondary of expert; y2 stages overlap expert tail)
    {
        cudaLaunchConfig_t cfg = {};
        cfg.gridDim = dim3(100, 2, BATCH);
        cfg.blockDim = dim3(256, 1, 1);
        cfg.attrs = pdl; cfg.numAttrs = 1;
        cudaLaunchKernelEx(&cfg, cv_mma_kernel<192, true>, (const float*)nullptr, b2, out);
    }
}

// round 14
// speedup vs baseline: 5.9853x; 1.0253x over previous
#include <cuda_runtime.h>
#include <cuda_fp16.h>
#include <cstdint>

#define C_HID 128
#define N_EXP 4
#define BATCH 16
#define HW 6400     // 80*80
#define W80 80

// ---------------- static scratch (no allocations allowed) ----------------
// half2 channel-pair packed activations: [b][cpair][pix] as u32(half2(c_even, c_odd))
__device__ uint32_t g_y2[BATCH * 128 * HW];     // cv1 out (a: cp 0..63, m: cp 64..127)
__device__ uint32_t g_moe2[BATCH * 64 * HW];    // gated expert mix
__device__ float    g_pooled[BATCH * C_HID];    // channel SUMS (exact fp32)
// half2 k-pair packed weights, oc-permuted
__device__ uint32_t g_w1t2[128 * 256];          // [kp][P(oc)]
__device__ uint32_t g_w2t2[192 * 256];          // [kp][P(oc)]
__device__ uint32_t g_wexpt2[N_EXP * 64 * 9 * 128]; // [e][icp][tap][P(oc)]

__device__ __forceinline__ float silu_f(float v) {
    return v / (1.0f + __expf(-v));
}

__device__ __forceinline__ uint32_t packh2(float lo, float hi) {
    __half2 h = __floats2half2_rn(lo, hi);
    return *(uint32_t*)&h;
}

// m16n8k16 fp16 -> fp32 accum
__device__ __forceinline__ void mma16(float* c, const uint32_t* a, const uint32_t* b) {
    asm volatile(
        "mma.sync.aligned.m16n8k16.row.col.f32.f16.f16.f32 "
        "{%0,%1,%2,%3}, {%4,%5,%6,%7}, {%8,%9}, {%0,%1,%2,%3};\n"
        : "+f"(c[0]), "+f"(c[1]), "+f"(c[2]), "+f"(c[3])
        : "r"(a[0]), "r"(a[1]), "r"(a[2]), "r"(a[3]),
          "r"(b[0]), "r"(b[1]));
}

__device__ __forceinline__ void cp16(uint32_t s, const void* g) {
    asm volatile("cp.async.cg.shared.global [%0], [%1], 16;\n" :: "r"(s), "l"(g));
}
__device__ __forceinline__ void cp4z(uint32_t s, const void* g, int srcsz) {
    asm volatile("cp.async.ca.shared.global [%0], [%1], 4, %2;\n" :: "r"(s), "l"(g), "r"(srcsz));
}
#define CP_COMMIT() asm volatile("cp.async.commit_group;\n" ::: "memory")
#define CP_WAIT2()  asm volatile("cp.async.wait_group 2;\n" ::: "memory")
#define CP_WAIT1()  asm volatile("cp.async.wait_group 1;\n" ::: "memory")
#define CP_WAIT0()  asm volatile("cp.async.wait_group 0;\n" ::: "memory")

// oc permutation within 16-groups: logical l -> 2*(l%8) + (l/8); fragment pair (g, g+8) adjacent.
__device__ __forceinline__ int permOC(int oc) {
    return (oc & ~15) | ((oc & 7) << 1) | ((oc >> 3) & 1);
}

// ---------------- kernel 0: weight transpose + half2 pack + oc-permute ----------------
__global__ void prep_kernel(const float* __restrict__ W1,
                            const float* __restrict__ W2,
                            const float* __restrict__ We) {
    cudaTriggerProgrammaticLaunchCompletion();
    int i = blockIdx.x * blockDim.x + threadIdx.x;
    if (i < BATCH * C_HID) g_pooled[i] = 0.0f;
    if (i < 128 * 256) {            // W1 [oc][ic] -> [kp][P(oc)] half2(ic=2kp, 2kp+1)
        int kp = i >> 8, oc = i & 255;
        g_w1t2[kp * 256 + permOC(oc)] = packh2(W1[oc * 256 + 2 * kp], W1[oc * 256 + 2 * kp + 1]);
    }
    if (i < 192 * 256) {            // W2 [oc][ic] -> [kp][P(oc)]
        int kp = i >> 8, oc = i & 255;
        g_w2t2[kp * 256 + permOC(oc)] = packh2(W2[oc * 384 + 2 * kp], W2[oc * 384 + 2 * kp + 1]);
    }
    if (i < N_EXP * 64 * 9 * 128) { // We [e][oc][ic][tap] -> [e][icp][tap][P(oc)]
        int oc = i & 127; int r = i >> 7;
        int tap = r % 9; r /= 9;
        int icp = r & 63; int e = r >> 6;
        size_t sb = ((size_t)(e * 128 + oc) * 128 + 2 * icp) * 9 + tap;
        g_wexpt2[(((e * 64 + icp) * 9) + tap) * 128 + permOC(oc)] = packh2(We[sb], We[sb + 9]);
    }
}

// ---------------- cv1 / cv2: fp16 mma GEMM, depth-3 cp.async pipeline, 4 smem buffers ----------
// Block tile M=128, N=64, stage = 16 kp (32 k). 8 warps 4(M) x 2(N), warp tile 32x32.
// 4 buffers (mod-4 rotation) so the issue at top of iter s targets (s+2)&3, whose readers
// (window s-2) are strictly behind the sync at top of iter s-1 — no cross-window race.
// PRECONV_B=false: cv1 (PDL: prefetch x, sync on prep), out = g_y2 half2 + fused pooling
// PRECONV_B=true:  cv2 (PDL: y2-stages run early, sync before issuing first moe stage), out = fp32
template <int KPT, bool PRECONV_B>
__global__ __launch_bounds__(256) void cv_mma_kernel(const float* __restrict__ X,
                                                     const float* __restrict__ bias,
                                                     float* __restrict__ outp) {
    __shared__ uint32_t As[4][16][136];   // [buf][kp][P(m)], stride 136 (mod32==8)
    __shared__ uint32_t Bs[4][16][72];    // [buf][kp][n],    stride 72  (mod32==8)

    const int b  = blockIdx.z;
    const int m0 = blockIdx.y * 128;
    const int n0 = blockIdx.x * 64;

    const int t    = threadIdx.x;
    const int warp = t >> 5, lane = t & 31;
    const int g    = lane >> 2, q = lane & 3;
    const int wm   = warp >> 1, wn = warp & 1;

    const uint32_t* wt = PRECONV_B ? g_w2t2 : g_w1t2;

    const int ar = t >> 5, ac4 = (t & 31) << 2;
    const int br_ = t >> 4, bc4 = (t & 15) << 2;

    float4 rBlo, rBhi;   // cv1 only: holds stage s+1 during window s
    float acc[2][4][4] = {};

    auto issueA = [&](int kp0, int buf) {
#pragma unroll
        for (int i = 0; i < 2; i++) {
            int r = ar + i * 8;
            cp16((uint32_t)__cvta_generic_to_shared(&As[buf][r][ac4]),
                 wt + (size_t)(kp0 + r) * 256 + m0 + ac4);
        }
    };
    auto issueB = [&](int kp0, int buf) {   // cv2
        int kgp = kp0 + br_;
        const uint32_t* src = (kgp < 128)
            ? (g_y2   + ((size_t)(b * 128 + kgp)) * HW + n0 + bc4)
            : (g_moe2 + ((size_t)(b * 64 + (kgp - 128))) * HW + n0 + bc4);
        cp16((uint32_t)__cvta_generic_to_shared(&Bs[buf][br_][bc4]), src);
    };
    auto loadB = [&](int kp0) {             // cv1: two fp32 channel rows
        const float* p = X + ((size_t)b * 256 + 2 * (kp0 + br_)) * HW + n0 + bc4;
        rBlo = *(const float4*)p;
        rBhi = *(const float4*)(p + HW);
    };
    auto storeB = [&](int buf) {
        *(uint4*)&Bs[buf][br_][bc4] = make_uint4(
            packh2(rBlo.x, rBhi.x), packh2(rBlo.y, rBhi.y),
            packh2(rBlo.z, rBhi.z), packh2(rBlo.w, rBhi.w));
    };

    // PDL prologue
    cudaTriggerProgrammaticLaunchCompletion();
    if (!PRECONV_B) {
        loadB(0);                         // x is a harness input: independent of prep
        cudaGridDependencySynchronize();  // wait prep (weights, pooled zero)
    }
    // cv2: no top sync — y2/w2t2 safe transitively (expert triggers after ITS sync)

    const int NST = KPT / 16;
    // prologue: stages 0 and 1 in flight
    issueA(0, 0);
    if (PRECONV_B) issueB(0, 0);
    CP_COMMIT();
    issueA(16, 1);
    if (PRECONV_B) issueB(16, 1);
    CP_COMMIT();
    if (!PRECONV_B) { storeB(0); loadB(16); }   // rB <- stage 1

    for (int s = 0; s < NST; s++) {
        const int buf = s & 3;
        if (s + 2 < NST) {
            if constexpr (PRECONV_B) {
                if (s + 2 == 8) cudaGridDependencySynchronize();  // before issuing first moe stage
            }
            issueA((s + 2) * 16, (s + 2) & 3);
            if (PRECONV_B) issueB((s + 2) * 16, (s + 2) & 3);
            CP_COMMIT();
        }
        if (s + 2 < NST) CP_WAIT2(); else if (s + 1 < NST) CP_WAIT1(); else CP_WAIT0();
        __syncthreads();   // As[buf]/Bs[buf] arrived (cp.async) or stored last window (cv1 B)

#pragma unroll
        for (int kk = 0; kk < 16; kk += 8) {
            uint32_t a[2][4], bb[4][2];
#pragma unroll
            for (int mt = 0; mt < 2; mt++) {
                int mb = wm * 32 + mt * 16 + 2 * g;
                uint2 lo = *(const uint2*)&As[buf][kk + q][mb];
                uint2 hi = *(const uint2*)&As[buf][kk + 4 + q][mb];
                a[mt][0] = lo.x; a[mt][1] = lo.y; a[mt][2] = hi.x; a[mt][3] = hi.y;
            }
#pragma unroll
            for (int nt = 0; nt < 4; nt++) {
                int nb = wn * 32 + nt * 8 + g;
                bb[nt][0] = Bs[buf][kk + q][nb];
                bb[nt][1] = Bs[buf][kk + 4 + q][nb];
            }
#pragma unroll
            for (int mt = 0; mt < 2; mt++)
#pragma unroll
                for (int nt = 0; nt < 4; nt++)
                    mma16(acc[mt][nt], a[mt], bb[nt]);
        }
        if (!PRECONV_B) {
            if (s + 1 < NST) storeB((s + 1) & 3);   // readers: window s+1; prior readers: window s-3
            if (s + 2 < NST) loadB((s + 2) * 16);
        }
    }

    // epilogue
#pragma unroll
    for (int mt = 0; mt < 2; mt++) {
#pragma unroll
        for (int half = 0; half < 2; half++) {
            int oc = m0 + wm * 32 + mt * 16 + g + half * 8;
            float bv = bias[oc];
            if (PRECONV_B) {
                float* op = outp + ((size_t)b * 256 + oc) * HW + n0 + wn * 32;
#pragma unroll
                for (int nt = 0; nt < 4; nt++) {
                    int col = nt * 8 + q * 2;
                    float v0 = silu_f(acc[mt][nt][half * 2 + 0] + bv);
                    float v1 = silu_f(acc[mt][nt][half * 2 + 1] + bv);
                    *(float2*)&op[col] = make_float2(v0, v1);
                }
            } else {
                uint32_t* yp = g_y2 + ((size_t)b * 128 + (oc >> 1)) * HW + n0 + wn * 32;
                float psum = 0.f;
#pragma unroll
                for (int nt = 0; nt < 4; nt++) {
                    int col = nt * 8 + q * 2;
                    float v0 = silu_f(acc[mt][nt][half * 2 + 0] + bv);
                    float v1 = silu_f(acc[mt][nt][half * 2 + 1] + bv);
                    psum += v0 + v1;
                    // pair channels (oc even in lane g, oc+1 in lane g^1): shfl over g bit0
                    float pv0 = __shfl_xor_sync(0xffffffffu, v0, 4);
                    float pv1 = __shfl_xor_sync(0xffffffffu, v1, 4);
                    if ((g & 1) == 0)
                        *(uint2*)&yp[col] = make_uint2(packh2(v0, pv0), packh2(v1, pv1));
                }
                if (m0 == 128) {
                    psum += __shfl_xor_sync(0xffffffffu, psum, 1);
                    psum += __shfl_xor_sync(0xffffffffu, psum, 2);
                    if (q == 0) atomicAdd(&g_pooled[b * C_HID + (oc - 128)], psum);
                }
            }
        }
    }
}

// ---------------- kernel 4: expert 3x3 convs, fp16 mma, fused gating, PDL ----------------
// Block = (row-pair, 1, batch). M=128 oc, N=160 (2 rows x 80). 8 warps 4(M)x2(row).
// Flat loop over 16 stages (2 experts x 8 ic-stages); cross-expert prefetch at the boundary.
// Two __syncthreads per iteration make the 2-buffer rotation race-free (prefetch target's
// readers finished before the post-compute sync of the previous iteration).
#define WS_ICP  1160                 // 9*128+8, ==8 mod 32
#define WS_BUF  (8 * WS_ICP)         // 9280
#define XS_ICP  328                  // 4*82, ==8 mod 32
#define XS_BUF  (8 * XS_ICP)         // 2624
#define XS_BASE (2 * WS_BUF)         // 18560
#define EXP_SMEM ((XS_BASE + 2 * XS_BUF) * 4)   // 95232 bytes

__global__ __launch_bounds__(256, 2) void expert_mma_kernel(const float* __restrict__ be,
                                                            const float* __restrict__ Wr,
                                                            const float* __restrict__ br) {
    extern __shared__ uint32_t dsm[];
    __shared__ float lg[N_EXP];
    __shared__ int   s_ae[2];
    __shared__ float s_ag[2];

    const int b  = blockIdx.z;
    const int r0 = blockIdx.x * 2;

    const int t    = threadIdx.x;
    const int warp = t >> 5, lane = t & 31;
    const int g    = lane >> 2, q = lane & 3;
    const int wm   = warp >> 1, wn = warp & 1;

    // PDL: wait for cv1 (pooled + y2), THEN trigger so cv2's early start implies cv1 done.
    cudaGridDependencySynchronize();
    cudaTriggerProgrammaticLaunchCompletion();

    // fused gating (redundant per block; deterministic — same pooled inputs everywhere)
    if (warp < N_EXP) {
        float s = 0.f;
#pragma unroll
        for (int j = 0; j < 4; j++) {
            int k = lane + j * 32;
            s += g_pooled[b * C_HID + k] * Wr[warp * C_HID + k];
        }
#pragma unroll
        for (int off = 16; off; off >>= 1) s += __shfl_xor_sync(0xffffffffu, s, off);
        if (lane == 0) lg[warp] = s * (1.0f / HW) + br[warp];
    }
    __syncthreads();
    if (t == 0) {
        float l[N_EXP];
#pragma unroll
        for (int e = 0; e < N_EXP; e++) l[e] = lg[e];
        int i1 = 0;
#pragma unroll
        for (int e = 1; e < N_EXP; e++) if (l[e] > l[i1]) i1 = e;
        int i2 = -1;
#pragma unroll
        for (int e = 0; e < N_EXP; e++) {
            if (e == i1) continue;
            if (i2 < 0 || l[e] > l[i2]) i2 = e;
        }
        float e2 = expf(l[i2] - l[i1]);
        float inv = 1.0f / (1.0f + e2);
        s_ae[0] = i1; s_ag[0] = inv;
        s_ae[1] = i2; s_ag[1] = e2 * inv;
    }
    __syncthreads();

    const uint32_t* minp = g_y2 + ((size_t)(b * 128 + 64)) * HW;  // m channels, pair-packed
    const uint32_t smem0 = (uint32_t)__cvta_generic_to_shared(dsm);

    const int oc4 = (t & 31) << 2;
    const int w0  = t >> 5;

    auto issueStage = [&](int e, int icp0, int buf) {
        uint32_t wdst = smem0 + (buf * WS_BUF) * 4;
#pragma unroll
        for (int i = 0; i < 9; i++) {
            int rem = w0 + i * 8;         // 0..71
            int tap = rem % 9, icp = rem / 9;
            cp16(wdst + (uint32_t)(icp * WS_ICP + tap * 128 + oc4) * 4,
                 g_wexpt2 + ((size_t)((e * 64 + icp0 + icp) * 9) + tap) * 128 + oc4);
        }
        uint32_t xdst = smem0 + (XS_BASE + buf * XS_BUF) * 4;
#pragma unroll
        for (int j = 0; j < 11; j++) {
            int idx = t + j * 256;
            if (idx < 8 * XS_ICP) {
                int icp = idx / XS_ICP;
                int rem = idx - icp * XS_ICP;
                int r   = rem / 82;
                int c   = rem - r * 82;
                int gr  = r0 - 1 + r;
                int gc  = c - 1;
                bool ok = ((unsigned)gr < 80u) && ((unsigned)gc < 80u);
                const uint32_t* src = minp + (size_t)(icp0 + icp) * HW + (ok ? gr * W80 + gc : 0);
                cp4z(xdst + (uint32_t)idx * 4, src, ok ? 4 : 0);
            }
        }
        CP_COMMIT();
    };

    float acc[2][10][4] = {};

    issueStage(s_ae[0], 0, 0);
    for (int s = 0; s < 16; s++) {
        const int buf = s & 1;
        const bool more = (s + 1 < 16);
        if (more) issueStage(s_ae[(s + 1) >> 3], ((s + 1) & 7) * 8, buf ^ 1);
        if (more) CP_WAIT1(); else CP_WAIT0();
        __syncthreads();

        const uint32_t* Wb = dsm + buf * WS_BUF;
        const uint32_t* Xb = dsm + XS_BASE + buf * XS_BUF;
#pragma unroll
        for (int tap = 0; tap < 9; tap++) {
            const int kh = tap / 3, kw = tap - kh * 3;
            uint32_t a[2][4];
            const uint32_t* wq0 = Wb + q * WS_ICP + tap * 128;
            const uint32_t* wq4 = Wb + (q + 4) * WS_ICP + tap * 128;
#pragma unroll
            for (int mt = 0; mt < 2; mt++) {
                int mb = wm * 32 + mt * 16 + 2 * g;
                uint2 lo = *(const uint2*)(wq0 + mb);
                uint2 hi = *(const uint2*)(wq4 + mb);
                a[mt][0] = lo.x; a[mt][1] = lo.y; a[mt][2] = hi.x; a[mt][3] = hi.y;
            }
            const uint32_t* xq0 = Xb + q * XS_ICP + (wn + kh) * 82;
            const uint32_t* xq4 = Xb + (q + 4) * XS_ICP + (wn + kh) * 82;
#pragma unroll
            for (int nt = 0; nt < 10; nt++) {
                int xc = nt * 8 + g + kw;
                uint32_t bb[2] = { xq0[xc], xq4[xc] };
                mma16(acc[0][nt], a[0], bb);
                mma16(acc[1][nt], a[1], bb);
            }
        }
        __syncthreads();

        if ((s & 7) == 7) {
            // expert epilogue: bias + SiLU + gate; runs while next expert's stage-0 loads land
            const int   ei = s >> 3;
            const int   e  = s_ae[ei];
            const float gt = s_ag[ei];
            const int   row = r0 + wn;
#pragma unroll
            for (int mt = 0; mt < 2; mt++) {
#pragma unroll
                for (int half = 0; half < 2; half++) {
                    int oc = wm * 32 + mt * 16 + g + half * 8;
                    float bv = be[e * C_HID + oc];
                    uint32_t* mp = g_moe2 + ((size_t)(b * 64 + (oc >> 1))) * HW + row * W80;
#pragma unroll
                    for (int nt = 0; nt < 10; nt++) {
                        int col = nt * 8 + q * 2;
                        float v0 = gt * silu_f(acc[mt][nt][half * 2 + 0] + bv);
                        float v1 = gt * silu_f(acc[mt][nt][half * 2 + 1] + bv);
                        float pv0 = __shfl_xor_sync(0xffffffffu, v0, 4);
                        float pv1 = __shfl_xor_sync(0xffffffffu, v1, 4);
                        if ((g & 1) == 0) {
                            if (ei == 1) {
                                uint2 o = *(uint2*)&mp[col];
                                __half2 h0 = *(__half2*)&o.x, h1 = *(__half2*)&o.y;
                                v0  += __low2float(h0);  pv0 += __high2float(h0);
                                v1  += __low2float(h1);  pv1 += __high2float(h1);
                            }
                            *(uint2*)&mp[col] = make_uint2(packh2(v0, pv0), packh2(v1, pv1));
                        }
                    }
                }
            }
            // reset accumulators for the next expert
#pragma unroll
            for (int mt = 0; mt < 2; mt++)
#pragma unroll
                for (int nt = 0; nt < 10; nt++)
#pragma unroll
                    for (int k = 0; k < 4; k++)
                        acc[mt][nt][k] = 0.f;
        }
    }
}

// ---------------- launch: single stream, PDL-chained ----------------
extern "C" void kernel_launch(void* const* d_in, const int* in_sizes, int n_in,
                              void* d_out, int out_size) {
    const float* x  = (const float*)d_in[0];
    const float* W1 = (const float*)d_in[1];
    const float* b1 = (const float*)d_in[2];
    const float* Wr = (const float*)d_in[3];
    const float* br = (const float*)d_in[4];
    const float* We = (const float*)d_in[5];
    const float* be = (const float*)d_in[6];
    const float* W2 = (const float*)d_in[7];
    const float* b2 = (const float*)d_in[8];
    float* out = (float*)d_out;

    cudaFuncSetAttribute(expert_mma_kernel,
                         cudaFuncAttributeMaxDynamicSharedMemorySize, EXP_SMEM);

    cudaLaunchAttribute pdl[1];
    pdl[0].id = cudaLaunchAttributeProgrammaticStreamSerialization;
    pdl[0].val.programmaticStreamSerializationAllowed = 1;

    // prep (primary)
    prep_kernel<<<(N_EXP * 64 * 9 * 128 + 255) / 256, 256>>>(W1, W2, We);

    // cv1 (PDL secondary of prep)
    {
        cudaLaunchConfig_t cfg = {};
        cfg.gridDim = dim3(100, 2, BATCH);
        cfg.blockDim = dim3(256, 1, 1);
        cfg.attrs = pdl; cfg.numAttrs = 1;
        cudaLaunchKernelEx(&cfg, cv_mma_kernel<128, false>, x, b1, (float*)nullptr);
    }
    // expert (PDL secondary of cv1; gating fused)
    {
        cudaLaunchConfig_t cfg = {};
        cfg.gridDim = dim3(40, 1, BATCH);
        cfg.blockDim = dim3(256, 1, 1);
        cfg.dynamicSmemBytes = EXP_SMEM;
        cfg.attrs = pdl; cfg.numAttrs = 1;
        cudaLaunchKernelEx(&cfg, expert_mma_kernel, be, Wr, br);
    }
    // cv2 (PDL secondary of expert; y2 stages overlap expert tail)
    {
        cudaLaunchConfig_t cfg = {};
        cfg.gridDim = dim3(100, 2, BATCH);
        cfg.blockDim = dim3(256, 1, 1);
        cfg.attrs = pdl; cfg.numAttrs = 1;
        cudaLaunchKernelEx(&cfg, cv_mma_kernel<192, true>, (const float*)nullptr, b2, out);
    }
}

// round 16
// speedup vs baseline: 6.0065x; 1.0036x over previous
#include <cuda_runtime.h>
#include <cuda_fp16.h>
#include <cstdint>

#define C_HID 128
#define N_EXP 4
#define BATCH 16
#define HW 6400     // 80*80
#define W80 80

// ---------------- static scratch (no allocations allowed) ----------------
// half2 channel-pair packed activations: [b][cpair][pix] as u32(half2(c_even, c_odd))
__device__ uint32_t g_y2[BATCH * 128 * HW];     // cv1 out (a: cp 0..63, m: cp 64..127)
__device__ uint32_t g_moe2[BATCH * 64 * HW];    // gated expert mix
__device__ float    g_pooled[BATCH * C_HID];    // channel SUMS (exact fp32)
// uint4-interleaved fragment-ready weights (see prep): each uint4 = {a0,a1,a2,a3} of an mma A-frag
__device__ __align__(16) uint32_t g_w1tQ[8 * 8 * 128 * 4];       // [stage8][row8][mp128] uint4
__device__ __align__(16) uint32_t g_w2tQ[12 * 8 * 128 * 4];      // [stage12][row8][mp128] uint4
__device__ __align__(16) uint32_t g_wexpQ[N_EXP * 8 * 4 * 9 * 64 * 4]; // [e][st8][qq4][tap9][mp64] uint4

__device__ __forceinline__ float silu_f(float v) {
    return v / (1.0f + __expf(-v));
}

__device__ __forceinline__ uint32_t packh2(float lo, float hi) {
    __half2 h = __floats2half2_rn(lo, hi);
    return *(uint32_t*)&h;
}

// m16n8k16 fp16 -> fp32 accum
__device__ __forceinline__ void mma16(float* c, const uint32_t* a, const uint32_t* b) {
    asm volatile(
        "mma.sync.aligned.m16n8k16.row.col.f32.f16.f16.f32 "
        "{%0,%1,%2,%3}, {%4,%5,%6,%7}, {%8,%9}, {%0,%1,%2,%3};\n"
        : "+f"(c[0]), "+f"(c[1]), "+f"(c[2]), "+f"(c[3])
        : "r"(a[0]), "r"(a[1]), "r"(a[2]), "r"(a[3]),
          "r"(b[0]), "r"(b[1]));
}

__device__ __forceinline__ void cp16(uint32_t s, const void* g) {
    asm volatile("cp.async.cg.shared.global [%0], [%1], 16;\n" :: "r"(s), "l"(g));
}
__device__ __forceinline__ void cp4z(uint32_t s, const void* g, int srcsz) {
    asm volatile("cp.async.ca.shared.global [%0], [%1], 4, %2;\n" :: "r"(s), "l"(g), "r"(srcsz));
}
#define CP_COMMIT() asm volatile("cp.async.commit_group;\n" ::: "memory")
#define CP_WAIT2()  asm volatile("cp.async.wait_group 2;\n" ::: "memory")
#define CP_WAIT1()  asm volatile("cp.async.wait_group 1;\n" ::: "memory")
#define CP_WAIT0()  asm volatile("cp.async.wait_group 0;\n" ::: "memory")

// oc permutation within 16-groups: logical l -> 2*(l%8) + (l/8); fragment pair (g, g+8) adjacent.
__device__ __forceinline__ int permOC(int oc) {
    return (oc & ~15) | ((oc & 7) << 1) | ((oc >> 3) & 1);
}

// ---------------- kernel 0: weight transpose + half2 pack + frag-interleave ----------------
__global__ void prep_kernel(const float* __restrict__ W1,
                            const float* __restrict__ W2,
                            const float* __restrict__ We) {
    cudaTriggerProgrammaticLaunchCompletion();
    int i = blockIdx.x * blockDim.x + threadIdx.x;
    if (i < BATCH * C_HID) g_pooled[i] = 0.0f;
    if (i < 128 * 256) {            // W1: (kp, oc) -> frag-interleaved
        int kp = i >> 8, oc = i & 255;
        uint32_t v = packh2(W1[oc * 256 + 2 * kp], W1[oc * 256 + 2 * kp + 1]);
        int stage = kp >> 4, r = kp & 15;
        int kk8 = r >> 3, q = r & 3, h = (r >> 2) & 1;
        int P = permOC(oc);
        g_w1tQ[((((stage * 2 + kk8) * 4 + q) * 128 + (P >> 1)) << 2) + h * 2 + (P & 1)] = v;
    }
    if (i < 192 * 256) {            // W2
        int kp = i >> 8, oc = i & 255;
        uint32_t v = packh2(W2[oc * 384 + 2 * kp], W2[oc * 384 + 2 * kp + 1]);
        int stage = kp >> 4, r = kp & 15;
        int kk8 = r >> 3, q = r & 3, h = (r >> 2) & 1;
        int P = permOC(oc);
        g_w2tQ[((((stage * 2 + kk8) * 4 + q) * 128 + (P >> 1)) << 2) + h * 2 + (P & 1)] = v;
    }
    if (i < N_EXP * 64 * 9 * 128) { // We: (e, icp, tap, oc) -> frag-interleaved
        int oc = i & 127; int r = i >> 7;
        int tap = r % 9; r /= 9;
        int icp = r & 63; int e = r >> 6;
        size_t sb = ((size_t)(e * 128 + oc) * 128 + 2 * icp) * 9 + tap;
        uint32_t v = packh2(We[sb], We[sb + 9]);
        int st = icp >> 3, qq = icp & 3, hh = (icp >> 2) & 1;
        int P = permOC(oc);
        g_wexpQ[(((((e * 8 + st) * 4 + qq) * 9 + tap) * 64 + (P >> 1)) << 2) + hh * 2 + (P & 1)] = v;
    }
}

// ---------------- cv1 / cv2: fp16 mma GEMM, depth-3 cp.async pipeline, 4 smem buffers ----------
// Block tile M=128, N=64, stage = 16 kp (32 k). 8 warps 4(M) x 2(N), warp tile 32x32.
// A tile smem: 8 rows (kk8*4+q) x 64 uint4, row stride 264 u32 (==8 mod 32) -> LDS.128 frags,
// bank-partition-perfect per phase. B tile unchanged.
// PRECONV_B=false: cv1 (PDL: prefetch x, sync on prep), out = g_y2 half2 + fused pooling
// PRECONV_B=true:  cv2 (PDL: y2-stages run early, sync before issuing first moe stage), out = fp32
template <int KPT, bool PRECONV_B>
__global__ __launch_bounds__(256) void cv_mma_kernel(const float* __restrict__ X,
                                                     const float* __restrict__ bias,
                                                     float* __restrict__ outp) {
    __shared__ uint32_t As[4][8 * 264];   // [buf][row(kk8*4+q) * 264]
    __shared__ uint32_t Bs[4][16][72];    // [buf][kp][n], stride 72 (mod32==8)

    const int b  = blockIdx.z;
    const int m0 = blockIdx.y * 128;
    const int n0 = blockIdx.x * 64;

    const int t    = threadIdx.x;
    const int warp = t >> 5, lane = t & 31;
    const int g    = lane >> 2, q = lane & 3;
    const int wm   = warp >> 1, wn = warp & 1;

    const uint32_t* wq = PRECONV_B ? g_w2tQ : g_w1tQ;

    const int br_ = t >> 4, bc4 = (t & 15) << 2;

    float4 rBlo, rBhi;   // cv1 only: holds stage s+1 during window s
    float acc[2][4][4] = {};

    auto issueA = [&](int st, int buf) {
#pragma unroll
        for (int i = 0; i < 2; i++) {
            int flat = t + i * 256;                 // 0..511
            int row = flat >> 6, col = flat & 63;
            cp16((uint32_t)__cvta_generic_to_shared(&As[buf][row * 264 + col * 4]),
                 wq + (((size_t)(st * 8 + row) * 128 + (m0 >> 1) + col) << 2));
        }
    };
    auto issueB = [&](int kp0, int buf) {   // cv2
        int kgp = kp0 + br_;
        const uint32_t* src = (kgp < 128)
            ? (g_y2   + ((size_t)(b * 128 + kgp)) * HW + n0 + bc4)
            : (g_moe2 + ((size_t)(b * 64 + (kgp - 128))) * HW + n0 + bc4);
        cp16((uint32_t)__cvta_generic_to_shared(&Bs[buf][br_][bc4]), src);
    };
    auto loadB = [&](int kp0) {             // cv1: two fp32 channel rows
        const float* p = X + ((size_t)b * 256 + 2 * (kp0 + br_)) * HW + n0 + bc4;
        rBlo = *(const float4*)p;
        rBhi = *(const float4*)(p + HW);
    };
    auto storeB = [&](int buf) {
        *(uint4*)&Bs[buf][br_][bc4] = make_uint4(
            packh2(rBlo.x, rBhi.x), packh2(rBlo.y, rBhi.y),
            packh2(rBlo.z, rBhi.z), packh2(rBlo.w, rBhi.w));
    };

    // PDL prologue
    cudaTriggerProgrammaticLaunchCompletion();
    if (!PRECONV_B) {
        loadB(0);                         // x is a harness input: independent of prep
        cudaGridDependencySynchronize();  // wait prep (weights, pooled zero)
    }
    // cv2: no top sync — y2/w2tQ safe transitively (expert triggers after ITS sync)

    const int NST = KPT / 16;
    // prologue: stages 0 and 1 in flight
    issueA(0, 0);
    if (PRECONV_B) issueB(0, 0);
    CP_COMMIT();
    issueA(1, 1);
    if (PRECONV_B) issueB(16, 1);
    CP_COMMIT();
    if (!PRECONV_B) { storeB(0); loadB(16); }   // rB <- stage 1

    for (int s = 0; s < NST; s++) {
        const int buf = s & 3;
        if (s + 2 < NST) {
            if constexpr (PRECONV_B) {
                if (s + 2 == 8) cudaGridDependencySynchronize();  // before issuing first moe stage
            }
            issueA(s + 2, (s + 2) & 3);
            if (PRECONV_B) issueB((s + 2) * 16, (s + 2) & 3);
            CP_COMMIT();
        }
        if (s + 2 < NST) CP_WAIT2(); else if (s + 1 < NST) CP_WAIT1(); else CP_WAIT0();
        __syncthreads();   // As[buf]/Bs[buf] arrived (cp.async) or stored last window (cv1 B)

#pragma unroll
        for (int kk8 = 0; kk8 < 2; kk8++) {
            const int kk = kk8 * 8;
            uint32_t a[2][4], bb[4][2];
            const uint32_t* Arow = &As[buf][(kk8 * 4 + q) * 264];
#pragma unroll
            for (int mt = 0; mt < 2; mt++) {
                uint4 a4 = *(const uint4*)&Arow[(wm * 16 + mt * 8 + g) * 4];
                a[mt][0] = a4.x; a[mt][1] = a4.y; a[mt][2] = a4.z; a[mt][3] = a4.w;
            }
#pragma unroll
            for (int nt = 0; nt < 4; nt++) {
                int nb = wn * 32 + nt * 8 + g;
                bb[nt][0] = Bs[buf][kk + q][nb];
                bb[nt][1] = Bs[buf][kk + 4 + q][nb];
            }
#pragma unroll
            for (int mt = 0; mt < 2; mt++)
#pragma unroll
                for (int nt = 0; nt < 4; nt++)
                    mma16(acc[mt][nt], a[mt], bb[nt]);
        }
        if (!PRECONV_B) {
            if (s + 1 < NST) storeB((s + 1) & 3);   // readers: window s+1; prior readers: s-3
            if (s + 2 < NST) loadB((s + 2) * 16);
        }
    }

    // epilogue
#pragma unroll
    for (int mt = 0; mt < 2; mt++) {
#pragma unroll
        for (int half = 0; half < 2; half++) {
            int oc = m0 + wm * 32 + mt * 16 + g + half * 8;
            float bv = bias[oc];
            if (PRECONV_B) {
                float* op = outp + ((size_t)b * 256 + oc) * HW + n0 + wn * 32;
#pragma unroll
                for (int nt = 0; nt < 4; nt++) {
                    int col = nt * 8 + q * 2;
                    float v0 = silu_f(acc[mt][nt][half * 2 + 0] + bv);
                    float v1 = silu_f(acc[mt][nt][half * 2 + 1] + bv);
                    *(float2*)&op[col] = make_float2(v0, v1);
                }
            } else {
                uint32_t* yp = g_y2 + ((size_t)b * 128 + (oc >> 1)) * HW + n0 + wn * 32;
                float psum = 0.f;
#pragma unroll
                for (int nt = 0; nt < 4; nt++) {
                    int col = nt * 8 + q * 2;
                    float v0 = silu_f(acc[mt][nt][half * 2 + 0] + bv);
                    float v1 = silu_f(acc[mt][nt][half * 2 + 1] + bv);
                    psum += v0 + v1;
                    // pair channels (oc even in lane g, oc+1 in lane g^1): shfl over g bit0
                    float pv0 = __shfl_xor_sync(0xffffffffu, v0, 4);
                    float pv1 = __shfl_xor_sync(0xffffffffu, v1, 4);
                    if ((g & 1) == 0)
                        *(uint2*)&yp[col] = make_uint2(packh2(v0, pv0), packh2(v1, pv1));
                }
                if (m0 == 128) {
                    psum += __shfl_xor_sync(0xffffffffu, psum, 1);
                    psum += __shfl_xor_sync(0xffffffffu, psum, 2);
                    if (q == 0) atomicAdd(&g_pooled[b * C_HID + (oc - 128)], psum);
                }
            }
        }
    }
}

// ---------------- kernel 4: expert 3x3 convs, fp16 mma, fused gating, PDL ----------------
// Block = (row-pair, 1, batch). M=128 oc, N=160 (2 rows x 80). 8 warps 4(M)x2(row).
// Flat loop over 16 stages (2 experts x 8 ic-stages); cross-expert prefetch at the boundary.
// Weights smem: [qq][tap][mp] uint4 (qq stride 2312 u32) -> A frag = 1 LDS.128.
// X smem: [qq][row][col][h] (qq stride 664 u32) -> B frag = 1 LDS.64. Both bank-partition-clean.
#define WS_QQ   2312                 // 9*64*4 + 8 pad, ==8 mod 32
#define WS_BUF  (4 * WS_QQ)          // 9248 u32
#define XS_QQ   664                  // 4*82*2 + 8 pad, ==24 mod 32
#define XS_BUF  (4 * XS_QQ)          // 2656 u32
#define XS_BASE (2 * WS_BUF)         // 18496
#define EXP_SMEM ((XS_BASE + 2 * XS_BUF) * 4)   // 95232 bytes

__global__ __launch_bounds__(256, 2) void expert_mma_kernel(const float* __restrict__ be,
                                                            const float* __restrict__ Wr,
                                                            const float* __restrict__ br) {
    extern __shared__ uint32_t dsm[];
    __shared__ float lg[N_EXP];
    __shared__ int   s_ae[2];
    __shared__ float s_ag[2];

    const int b  = blockIdx.z;
    const int r0 = blockIdx.x * 2;

    const int t    = threadIdx.x;
    const int warp = t >> 5, lane = t & 31;
    const int g    = lane >> 2, q = lane & 3;
    const int wm   = warp >> 1, wn = warp & 1;

    // PDL: wait for cv1 (pooled + y2), THEN trigger so cv2's early start implies cv1 done.
    cudaGridDependencySynchronize();
    cudaTriggerProgrammaticLaunchCompletion();

    // fused gating (redundant per block; deterministic — same pooled inputs everywhere)
    if (warp < N_EXP) {
        float s = 0.f;
#pragma unroll
        for (int j = 0; j < 4; j++) {
            int k = lane + j * 32;
            s += g_pooled[b * C_HID + k] * Wr[warp * C_HID + k];
        }
#pragma unroll
        for (int off = 16; off; off >>= 1) s += __shfl_xor_sync(0xffffffffu, s, off);
        if (lane == 0) lg[warp] = s * (1.0f / HW) + br[warp];
    }
    __syncthreads();
    if (t == 0) {
        float l[N_EXP];
#pragma unroll
        for (int e = 0; e < N_EXP; e++) l[e] = lg[e];
        int i1 = 0;
#pragma unroll
        for (int e = 1; e < N_EXP; e++) if (l[e] > l[i1]) i1 = e;
        int i2 = -1;
#pragma unroll
        for (int e = 0; e < N_EXP; e++) {
            if (e == i1) continue;
            if (i2 < 0 || l[e] > l[i2]) i2 = e;
        }
        float e2 = expf(l[i2] - l[i1]);
        float inv = 1.0f / (1.0f + e2);
        s_ae[0] = i1; s_ag[0] = inv;
        s_ae[1] = i2; s_ag[1] = e2 * inv;
    }
    __syncthreads();

    const uint32_t* minp = g_y2 + ((size_t)(b * 128 + 64)) * HW;  // m channels, pair-packed
    const uint32_t smem0 = (uint32_t)__cvta_generic_to_shared(dsm);

    auto issueStage = [&](int e, int st, int buf) {
        // weights: 4 qq x 9 tap x 64 mp uint4 = 2304 cp16s (9 per thread)
        uint32_t wdst = smem0 + (buf * WS_BUF) * 4;
#pragma unroll
        for (int i = 0; i < 9; i++) {
            int flat = t + i * 256;           // 0..2303
            int mp   = flat & 63;
            int rest = flat >> 6;             // 0..35
            int tap  = rest % 9, qq = rest / 9;
            cp16(wdst + (uint32_t)(qq * WS_QQ + (tap * 64 + mp) * 4) * 4,
                 g_wexpQ + ((((size_t)((e * 8 + st) * 4 + qq) * 9 + tap) * 64 + mp) << 2));
        }
        // input: 8 icp x 4 rows x 82 cols, 4B copies with border zero-fill
        uint32_t xdst = smem0 + (XS_BASE + buf * XS_BUF) * 4;
#pragma unroll
        for (int j = 0; j < 11; j++) {
            int idx = t + j * 256;
            if (idx < 8 * 328) {
                int icp = idx / 328;
                int rem = idx - icp * 328;
                int r   = rem / 82;
                int c   = rem - r * 82;
                int gr  = r0 - 1 + r;
                int gc  = c - 1;
                bool ok = ((unsigned)gr < 80u) && ((unsigned)gc < 80u);
                const uint32_t* src = minp + (size_t)(st * 8 + icp) * HW + (ok ? gr * W80 + gc : 0);
                int qq = icp & 3, hh = icp >> 2;
                cp4z(xdst + (uint32_t)(qq * XS_QQ + (r * 82 + c) * 2 + hh) * 4, src, ok ? 4 : 0);
            }
        }
        CP_COMMIT();
    };

    float acc[2][10][4] = {};

    issueStage(s_ae[0], 0, 0);
    for (int s = 0; s < 16; s++) {
        const int buf = s & 1;
        const bool more = (s + 1 < 16);
        if (more) issueStage(s_ae[(s + 1) >> 3], (s + 1) & 7, buf ^ 1);
        if (more) CP_WAIT1(); else CP_WAIT0();
        __syncthreads();

        const uint32_t* Wb = dsm + buf * WS_BUF;
        const uint32_t* Xb = dsm + XS_BASE + buf * XS_BUF;
#pragma unroll
        for (int tap = 0; tap < 9; tap++) {
            const int kh = tap / 3, kw = tap - kh * 3;
            uint32_t a[2][4];
            const uint32_t* wrow = Wb + q * WS_QQ + tap * 256;
#pragma unroll
            for (int mt = 0; mt < 2; mt++) {
                uint4 a4 = *(const uint4*)&wrow[(wm * 16 + mt * 8 + g) * 4];
                a[mt][0] = a4.x; a[mt][1] = a4.y; a[mt][2] = a4.z; a[mt][3] = a4.w;
            }
            const uint32_t* xrow = Xb + q * XS_QQ + (wn + kh) * 164;   // *82*2
#pragma unroll
            for (int nt = 0; nt < 10; nt++) {
                uint2 b2 = *(const uint2*)&xrow[(nt * 8 + g + kw) * 2];
                uint32_t bb[2] = { b2.x, b2.y };
                mma16(acc[0][nt], a[0], bb);
                mma16(acc[1][nt], a[1], bb);
            }
        }
        __syncthreads();

        if ((s & 7) == 7) {
            // expert epilogue: bias + SiLU + gate; runs while next expert's stage-0 loads land
            const int   ei = s >> 3;
            const int   e  = s_ae[ei];
            const float gt = s_ag[ei];
            const int   row = r0 + wn;
#pragma unroll
            for (int mt = 0; mt < 2; mt++) {
#pragma unroll
                for (int half = 0; half < 2; half++) {
                    int oc = wm * 32 + mt * 16 + g + half * 8;
                    float bv = be[e * C_HID + oc];
                    uint32_t* mp = g_moe2 + ((size_t)(b * 64 + (oc >> 1))) * HW + row * W80;
#pragma unroll
                    for (int nt = 0; nt < 10; nt++) {
                        int col = nt * 8 + q * 2;
                        float v0 = gt * silu_f(acc[mt][nt][half * 2 + 0] + bv);
                        float v1 = gt * silu_f(acc[mt][nt][half * 2 + 1] + bv);
                        float pv0 = __shfl_xor_sync(0xffffffffu, v0, 4);
                        float pv1 = __shfl_xor_sync(0xffffffffu, v1, 4);
                        if ((g & 1) == 0) {
                            if (ei == 1) {
                                uint2 o = *(uint2*)&mp[col];
                                __half2 h0 = *(__half2*)&o.x, h1 = *(__half2*)&o.y;
                                v0  += __low2float(h0);  pv0 += __high2float(h0);
                                v1  += __low2float(h1);  pv1 += __high2float(h1);
                            }
                            *(uint2*)&mp[col] = make_uint2(packh2(v0, pv0), packh2(v1, pv1));
                        }
                    }
                }
            }
            // reset accumulators for the next expert
#pragma unroll
            for (int mt = 0; mt < 2; mt++)
#pragma unroll
                for (int nt = 0; nt < 10; nt++)
#pragma unroll
                    for (int k = 0; k < 4; k++)
                        acc[mt][nt][k] = 0.f;
        }
    }
}

// ---------------- launch: single stream, PDL-chained ----------------
extern "C" void kernel_launch(void* const* d_in, const int* in_sizes, int n_in,
                              void* d_out, int out_size) {
    const float* x  = (const float*)d_in[0];
    const float* W1 = (const float*)d_in[1];
    const float* b1 = (const float*)d_in[2];
    const float* Wr = (const float*)d_in[3];
    const float* br = (const float*)d_in[4];
    const float* We = (const float*)d_in[5];
    const float* be = (const float*)d_in[6];
    const float* W2 = (const float*)d_in[7];
    const float* b2 = (const float*)d_in[8];
    float* out = (float*)d_out;

    cudaFuncSetAttribute(expert_mma_kernel,
                         cudaFuncAttributeMaxDynamicSharedMemorySize, EXP_SMEM);

    cudaLaunchAttribute pdl[1];
    pdl[0].id = cudaLaunchAttributeProgrammaticStreamSerialization;
    pdl[0].val.programmaticStreamSerializationAllowed = 1;

    // prep (primary)
    prep_kernel<<<(N_EXP * 64 * 9 * 128 + 255) / 256, 256>>>(W1, W2, We);

    // cv1 (PDL secondary of prep)
    {
        cudaLaunchConfig_t cfg = {};
        cfg.gridDim = dim3(100, 2, BATCH);
        cfg.blockDim = dim3(256, 1, 1);
        cfg.attrs = pdl; cfg.numAttrs = 1;
        cudaLaunchKernelEx(&cfg, cv_mma_kernel<128, false>, x, b1, (float*)nullptr);
    }
    // expert (PDL secondary of cv1; gating fused)
    {
        cudaLaunchConfig_t cfg = {};
        cfg.gridDim = dim3(40, 1, BATCH);
        cfg.blockDim = dim3(256, 1, 1);
        cfg.dynamicSmemBytes = EXP_SMEM;
        cfg.attrs = pdl; cfg.numAttrs = 1;
        cudaLaunchKernelEx(&cfg, expert_mma_kernel, be, Wr, br);
    }
    // cv2 (PDL secondary of expert; y2 stages overlap expert tail)
    {
        cudaLaunchConfig_t cfg = {};
        cfg.gridDim = dim3(100, 2, BATCH);
        cfg.blockDim = dim3(256, 1, 1);
        cfg.attrs = pdl; cfg.numAttrs = 1;
        cudaLaunchKernelEx(&cfg, cv_mma_kernel<192, true>, (const float*)nullptr, b2, out);
    }
}